// round 6
// baseline (speedup 1.0000x reference)
#include <cuda_runtime.h>
#include <cuda_bf16.h>
#include <math.h>
#include <stdint.h>

// Problem constants
#define BATCH 2
#define TSEQ  1024
#define DIMM  512
#define NHEAD 8
#define DKH   64
#define NROWS (BATCH * TSEQ)   // 2048

// ---------------------------------------------------------------------------
// Scratch (__device__ globals)
// ---------------------------------------------------------------------------
__device__ __align__(16) float g_G[NROWS * DIMM];
__device__ __align__(16) float g_Opart0[NROWS * DIMM];
__device__ __align__(16) float g_Opart1[NROWS * DIMM];
__device__ __align__(16) float g_zpart0[NROWS * NHEAD];
__device__ __align__(16) float g_zpart1[NROWS * NHEAD];

__device__ __align__(16) __nv_bfloat16 g_Xhi[NROWS * DIMM];
__device__ __align__(16) __nv_bfloat16 g_Xlo[NROWS * DIMM];
__device__ __align__(16) __nv_bfloat16 g_Qh[NROWS * DIMM];
__device__ __align__(16) __nv_bfloat16 g_Ql[NROWS * DIMM];
__device__ __align__(16) __nv_bfloat16 g_Kh[NROWS * DIMM];
__device__ __align__(16) __nv_bfloat16 g_Kl[NROWS * DIMM];
// V transposed: [(b*8+h)*64 + d][t]
__device__ __align__(16) __nv_bfloat16 g_Vth[NROWS * DIMM];
__device__ __align__(16) __nv_bfloat16 g_Vtl[NROWS * DIMM];
__device__ __align__(16) __nv_bfloat16 g_Ohi[NROWS * DIMM];
__device__ __align__(16) __nv_bfloat16 g_Olo[NROWS * DIMM];
// transposed weights [n][k] (K-major); 4 projection weights + Wo
__device__ __align__(16) __nv_bfloat16 g_Wthi[4 * DIMM * DIMM];
__device__ __align__(16) __nv_bfloat16 g_Wtlo[4 * DIMM * DIMM];
__device__ __align__(16) __nv_bfloat16 g_Wothi[DIMM * DIMM];
__device__ __align__(16) __nv_bfloat16 g_Wotlo[DIMM * DIMM];

// ---------------------------------------------------------------------------
// helpers
// ---------------------------------------------------------------------------
__device__ __forceinline__ uint32_t smem_u32(const void* p) {
    uint32_t a;
    asm("{ .reg .u64 t; cvta.to.shared.u64 t, %1; cvt.u32.u64 %0, t; }" : "=r"(a) : "l"(p));
    return a;
}
__device__ __forceinline__ void cp_async16(uint32_t dst, const void* src) {
    asm volatile("cp.async.cg.shared.global [%0], [%1], 16;" :: "r"(dst), "l"(src));
}
__device__ __forceinline__ void cp_commit() {
    asm volatile("cp.async.commit_group;" ::: "memory");
}
template <int N>
__device__ __forceinline__ void cp_wait() {
    asm volatile("cp.async.wait_group %0;" :: "n"(N) : "memory");
}
__device__ __forceinline__ void ldsm4(uint32_t* r, uint32_t addr) {
    asm volatile("ldmatrix.sync.aligned.m8n8.x4.shared.b16 {%0,%1,%2,%3}, [%4];"
        : "=r"(r[0]), "=r"(r[1]), "=r"(r[2]), "=r"(r[3]) : "r"(addr));
}
__device__ __forceinline__ void mma16816(float* c,
                                         uint32_t a0, uint32_t a1, uint32_t a2, uint32_t a3,
                                         uint32_t b0, uint32_t b1) {
    asm volatile(
        "mma.sync.aligned.m16n8k16.row.col.f32.bf16.bf16.f32 "
        "{%0,%1,%2,%3}, {%4,%5,%6,%7}, {%8,%9}, {%0,%1,%2,%3};"
        : "+f"(c[0]), "+f"(c[1]), "+f"(c[2]), "+f"(c[3])
        : "r"(a0), "r"(a1), "r"(a2), "r"(a3), "r"(b0), "r"(b1));
}
__device__ __forceinline__ void split_bf16(float v, __nv_bfloat16& h, __nv_bfloat16& l) {
    h = __float2bfloat16(v);
    l = __float2bfloat16(v - __bfloat162float(h));
}
__device__ __forceinline__ uint32_t pack2(__nv_bfloat16 a, __nv_bfloat16 b) {
    __nv_bfloat162 t = __halves2bfloat162(a, b);
    return *(uint32_t*)&t;
}

// ---------------------------------------------------------------------------
// merged preprocessing: z<5 -> weight transpose+split; z>=5 -> x split
// ---------------------------------------------------------------------------
__global__ void __launch_bounds__(256) prep_kernel(
    const float* __restrict__ x,
    const float* __restrict__ Wq, const float* __restrict__ Wk,
    const float* __restrict__ Wv, const float* __restrict__ Wg,
    const float* __restrict__ Wo)
{
    if (blockIdx.z < 5) {
        __shared__ float t[32][33];
        const int w = blockIdx.z;
        const float* __restrict__ W = (w == 0) ? Wq : (w == 1) ? Wk : (w == 2) ? Wv : (w == 3) ? Wg : Wo;
        __nv_bfloat16* __restrict__ Hi = (w < 4) ? (g_Wthi + (size_t)w * DIMM * DIMM) : g_Wothi;
        __nv_bfloat16* __restrict__ Lo = (w < 4) ? (g_Wtlo + (size_t)w * DIMM * DIMM) : g_Wotlo;

        const int tx = threadIdx.x & 31, ty = threadIdx.x >> 5;
        const int n0 = blockIdx.x * 32, k0 = blockIdx.y * 32;
#pragma unroll
        for (int j = 0; j < 4; j++)
            t[ty + 8 * j][tx] = W[(size_t)(k0 + ty + 8 * j) * DIMM + n0 + tx];
        __syncthreads();
#pragma unroll
        for (int j = 0; j < 4; j++) {
            float v = t[tx][ty + 8 * j];
            __nv_bfloat16 h, l; split_bf16(v, h, l);
            size_t o = (size_t)(n0 + ty + 8 * j) * DIMM + k0 + tx;
            Hi[o] = h; Lo[o] = l;
        }
    } else {
        int bid = (blockIdx.z - 5) * 256 + blockIdx.y * 16 + blockIdx.x;
        int i4 = (bid * 256 + threadIdx.x) * 4;
        float4 v = *(const float4*)(x + i4);
        __nv_bfloat16 h0, h1, h2, h3, l0, l1, l2, l3;
        split_bf16(v.x, h0, l0); split_bf16(v.y, h1, l1);
        split_bf16(v.z, h2, l2); split_bf16(v.w, h3, l3);
        *(__nv_bfloat162*)(g_Xhi + i4)     = __halves2bfloat162(h0, h1);
        *(__nv_bfloat162*)(g_Xhi + i4 + 2) = __halves2bfloat162(h2, h3);
        *(__nv_bfloat162*)(g_Xlo + i4)     = __halves2bfloat162(l0, l1);
        *(__nv_bfloat162*)(g_Xlo + i4 + 2) = __halves2bfloat162(l2, l3);
    }
}

// ---------------------------------------------------------------------------
// split-bf16 HMMA GEMM core with ldmatrix fragment loads
// mode: 0 plain float out, 1 relu->bf16 hi/lo, 2 split->transposed Vt, 3 sigmoid->float
// ---------------------------------------------------------------------------
#define PADK 40
#define BUF_ELEMS (128 * PADK)
#define STAGE_ELEMS (4 * BUF_ELEMS)
#define GEMM_SMEM_BYTES (2 * STAGE_ELEMS * 2)  // 81920

__device__ __forceinline__ void mma_gemm_tile(
    const __nv_bfloat16* __restrict__ Ahi, const __nv_bfloat16* __restrict__ Alo,
    const __nv_bfloat16* __restrict__ Bhi, const __nv_bfloat16* __restrict__ Blo,
    int mode, int m0, int n0,
    float* __restrict__ fout, __nv_bfloat16* __restrict__ ohi,
    __nv_bfloat16* __restrict__ olo, const float* __restrict__ bias)
{
    extern __shared__ __nv_bfloat16 sm[];
    const uint32_t smb = smem_u32(sm);

    const int tid = threadIdx.x;
    const int wid = tid >> 5;
    const int lane = tid & 31;
    const int wm = wid >> 2;
    const int wn = wid & 3;
    const int gid = lane >> 2;
    const int qid = lane & 3;

    // ldmatrix per-thread address offsets (bytes)
    const uint32_t a_off = (uint32_t)((wm * 64 + (lane & 15)) * PADK + (lane >> 4) * 8) * 2;
    const uint32_t b_off = (uint32_t)((wn * 32 + (lane & 7)) * PADK + (lane >> 3) * 8) * 2;

    float c[4][4][4];
#pragma unroll
    for (int i = 0; i < 4; i++)
#pragma unroll
        for (int j = 0; j < 4; j++)
#pragma unroll
            for (int k = 0; k < 4; k++) c[i][j][k] = 0.f;

    auto prefetch = [&](int chunk, int stage) {
        const int k0 = chunk * 32;
#pragma unroll
        for (int t = 0; t < 2; t++) {
            int id = tid + t * 256;
            int row = id >> 2, seg = id & 3;
            uint32_t soff = (uint32_t)(row * PADK + seg * 8) * 2;
            uint32_t sb = smb + (uint32_t)stage * (STAGE_ELEMS * 2) + soff;
            size_t ao = (size_t)(m0 + row) * DIMM + k0 + seg * 8;
            size_t bo = (size_t)(n0 + row) * DIMM + k0 + seg * 8;
            cp_async16(sb + 0 * (BUF_ELEMS * 2), Ahi + ao);
            cp_async16(sb + 1 * (BUF_ELEMS * 2), Alo + ao);
            cp_async16(sb + 2 * (BUF_ELEMS * 2), Bhi + bo);
            cp_async16(sb + 3 * (BUF_ELEMS * 2), Blo + bo);
        }
        cp_commit();
    };

    prefetch(0, 0);

    for (int chunk = 0; chunk < 16; chunk++) {
        const int stage = chunk & 1;
        if (chunk + 1 < 16) {
            prefetch(chunk + 1, stage ^ 1);
            cp_wait<1>();
        } else {
            cp_wait<0>();
        }
        __syncthreads();

        const uint32_t sA_hi = smb + (uint32_t)stage * (STAGE_ELEMS * 2);
        const uint32_t sA_lo = sA_hi + BUF_ELEMS * 2;
        const uint32_t sB_hi = sA_hi + 2 * (BUF_ELEMS * 2);
        const uint32_t sB_lo = sA_hi + 3 * (BUF_ELEMS * 2);

        // B fragments for the whole K=32 chunk: regs [ks*2], [ks*2+1]
        uint32_t bh[4][4], bl[4][4];
#pragma unroll
        for (int nf = 0; nf < 4; nf++) {
            const uint32_t bo = b_off + (uint32_t)nf * (8 * PADK * 2);
            ldsm4(bh[nf], sB_hi + bo);
            ldsm4(bl[nf], sB_lo + bo);
        }

#pragma unroll
        for (int ks = 0; ks < 2; ks++) {
            uint32_t ahi[4][4], alo[4][4];
#pragma unroll
            for (int mf = 0; mf < 4; mf++) {
                const uint32_t ao = a_off + (uint32_t)mf * (16 * PADK * 2) + (uint32_t)ks * 32;
                ldsm4(ahi[mf], sA_hi + ao);
                ldsm4(alo[mf], sA_lo + ao);
            }
#pragma unroll
            for (int nf = 0; nf < 4; nf++) {
                const uint32_t b0h = bh[nf][ks * 2], b1h = bh[nf][ks * 2 + 1];
                const uint32_t b0l = bl[nf][ks * 2], b1l = bl[nf][ks * 2 + 1];
#pragma unroll
                for (int mf = 0; mf < 4; mf++) {
                    mma16816(c[mf][nf], ahi[mf][0], ahi[mf][1], ahi[mf][2], ahi[mf][3], b0h, b1h);
                    mma16816(c[mf][nf], ahi[mf][0], ahi[mf][1], ahi[mf][2], ahi[mf][3], b0l, b1l);
                    mma16816(c[mf][nf], alo[mf][0], alo[mf][1], alo[mf][2], alo[mf][3], b0h, b1h);
                }
            }
        }
        __syncthreads();
    }

#pragma unroll
    for (int mf = 0; mf < 4; mf++) {
#pragma unroll
        for (int nf = 0; nf < 4; nf++) {
            int m = m0 + wm * 64 + mf * 16 + gid;
            int n = n0 + wn * 32 + nf * 8 + qid * 2;
            float v0 = c[mf][nf][0], v1 = c[mf][nf][1];
            float v2 = c[mf][nf][2], v3 = c[mf][nf][3];
            if (mode == 0) {
                *(float2*)(fout + (size_t)m * DIMM + n)       = make_float2(v0, v1);
                *(float2*)(fout + (size_t)(m + 8) * DIMM + n) = make_float2(v2, v3);
            } else if (mode == 1) {
                v0 = fmaxf(v0, 0.f); v1 = fmaxf(v1, 0.f);
                v2 = fmaxf(v2, 0.f); v3 = fmaxf(v3, 0.f);
                __nv_bfloat16 h0, h1, h2, h3, l0, l1, l2, l3;
                split_bf16(v0, h0, l0); split_bf16(v1, h1, l1);
                split_bf16(v2, h2, l2); split_bf16(v3, h3, l3);
                *(__nv_bfloat162*)(ohi + (size_t)m * DIMM + n)       = __halves2bfloat162(h0, h1);
                *(__nv_bfloat162*)(ohi + (size_t)(m + 8) * DIMM + n) = __halves2bfloat162(h2, h3);
                *(__nv_bfloat162*)(olo + (size_t)m * DIMM + n)       = __halves2bfloat162(l0, l1);
                *(__nv_bfloat162*)(olo + (size_t)(m + 8) * DIMM + n) = __halves2bfloat162(l2, l3);
            } else if (mode == 2) {
                int bb = m >> 10, tt = m & 1023;
                int hh = n >> 6, dd = n & 63;
                size_t base = ((size_t)((bb * 8 + hh) * 64 + dd)) * 1024 + tt;
                __nv_bfloat16 h0, h1, h2, h3, l0, l1, l2, l3;
                split_bf16(v0, h0, l0); split_bf16(v1, h1, l1);
                split_bf16(v2, h2, l2); split_bf16(v3, h3, l3);
                ohi[base] = h0;        olo[base] = l0;
                ohi[base + 1024] = h1; olo[base + 1024] = l1;
                ohi[base + 8] = h2;    olo[base + 8] = l2;
                ohi[base + 1032] = h3; olo[base + 1032] = l3;
            } else {
                float b0 = bias[n], b1 = bias[n + 1];
                v0 = 1.f / (1.f + expf(-(v0 + b0)));
                v1 = 1.f / (1.f + expf(-(v1 + b1)));
                v2 = 1.f / (1.f + expf(-(v2 + b0)));
                v3 = 1.f / (1.f + expf(-(v3 + b1)));
                *(float2*)(fout + (size_t)m * DIMM + n)       = make_float2(v0, v1);
                *(float2*)(fout + (size_t)(m + 8) * DIMM + n) = make_float2(v2, v3);
            }
        }
    }
}

__global__ void __launch_bounds__(256) mma_proj_kernel(const float* __restrict__ bg)
{
    const int zi = blockIdx.z;
    const __nv_bfloat16* Bh = g_Wthi + (size_t)zi * DIMM * DIMM;
    const __nv_bfloat16* Bl = g_Wtlo + (size_t)zi * DIMM * DIMM;
    const int m0 = blockIdx.y * 128, n0 = blockIdx.x * 128;
    if (zi == 0)
        mma_gemm_tile(g_Xhi, g_Xlo, Bh, Bl, 1, m0, n0, nullptr, g_Qh, g_Ql, nullptr);
    else if (zi == 1)
        mma_gemm_tile(g_Xhi, g_Xlo, Bh, Bl, 1, m0, n0, nullptr, g_Kh, g_Kl, nullptr);
    else if (zi == 2)
        mma_gemm_tile(g_Xhi, g_Xlo, Bh, Bl, 2, m0, n0, nullptr, g_Vth, g_Vtl, nullptr);
    else
        mma_gemm_tile(g_Xhi, g_Xlo, Bh, Bl, 3, m0, n0, g_G, nullptr, nullptr, bg);
}

__global__ void __launch_bounds__(256) mma_out_kernel(float* __restrict__ out)
{
    mma_gemm_tile(g_Ohi, g_Olo, g_Wothi, g_Wotlo, 0, blockIdx.y * 128, blockIdx.x * 128,
                  out, nullptr, nullptr, nullptr);
}

// ---------------------------------------------------------------------------
// HMMA cosformer attention, split-K (2 segments per qtile), ldmatrix loads
// ---------------------------------------------------------------------------
#define APAD 72
#define ATILE (64 * APAD)
#define AQH 0
#define AQL (ATILE)
#define AKH (2 * ATILE)
#define AKL (4 * ATILE)
#define AVH (6 * ATILE)
#define AVL (8 * ATILE)
#define ATRIG_C (10 * ATILE * 2)
#define ATTN2_SMEM_BYTES (10 * ATILE * 2 + 2 * 2 * 64 * 4)

__global__ void __launch_bounds__(128) attn3_kernel()
{
    extern __shared__ __nv_bfloat16 asm_[];
    const uint32_t smb = smem_u32(asm_);
    float* cks = (float*)((char*)asm_ + ATRIG_C);
    float* sks = cks + 128;

    const int i = 15 - (blockIdx.x >> 1);
    const int seg = blockIdx.x & 1;
    const int h = blockIdx.y;
    const int b = blockIdx.z;
    const int tid = threadIdx.x;
    const int wid = tid >> 5;
    const int lane = tid & 31;
    const int gid = lane >> 2;
    const int qid = lane & 3;

    const int nj = i + 1;
    const int hhalf = (nj + 1) >> 1;
    const int jlo = seg ? hhalf : 0;
    const int jhi = seg ? nj : hhalf;

    const int qrow0 = b * TSEQ + i * 64;
    const float ANG = (float)(3.14159265358979323846 / 2048.0);

    // prologue: load Q tile (hi/lo) + first K/V stage in one cp group
    {
#pragma unroll
        for (int t = 0; t < 4; t++) {
            int id = tid + t * 128;
            int row = id >> 3, sgm = id & 7;
            size_t src = (size_t)(qrow0 + row) * DIMM + h * DKH + sgm * 8;
            uint32_t so = (uint32_t)(row * APAD + sgm * 8) * 2;
            cp_async16(smb + AQH * 2 + so, g_Qh + src);
            cp_async16(smb + AQL * 2 + so, g_Ql + src);
        }
    }
    auto prefetch_kv = [&](int j, int s) {
#pragma unroll
        for (int t = 0; t < 4; t++) {
            int id = tid + t * 128;
            int row = id >> 3, sgm = id & 7;
            uint32_t so = (uint32_t)(row * APAD + sgm * 8) * 2 + (uint32_t)s * (ATILE * 2);
            size_t ksrc = (size_t)(b * TSEQ + j * 64 + row) * DIMM + h * DKH + sgm * 8;
            cp_async16(smb + AKH * 2 + so, g_Kh + ksrc);
            cp_async16(smb + AKL * 2 + so, g_Kl + ksrc);
            size_t vsrc = (size_t)((b * 8 + h) * 64 + row) * TSEQ + j * 64 + sgm * 8;
            cp_async16(smb + AVH * 2 + so, g_Vth + vsrc);
            cp_async16(smb + AVL * 2 + so, g_Vtl + vsrc);
        }
    };
    if (jlo < jhi) prefetch_kv(jlo, 0);
    cp_commit();

    float cq0, sq0, cq1, sq1;
    {
        float a0 = (float)(i * 64 + wid * 16 + gid) * ANG;
        float a1 = (float)(i * 64 + wid * 16 + gid + 8) * ANG;
        sincosf(a0, &sq0, &cq0);
        sincosf(a1, &sq1, &cq1);
    }

    float oacc[8][4];
#pragma unroll
    for (int nf = 0; nf < 8; nf++)
#pragma unroll
        for (int k = 0; k < 4; k++) oacc[nf][k] = 0.f;
    float z0 = 0.f, z1 = 0.f;

    // ldmatrix per-thread offsets (bytes)
    const uint32_t q_off = (uint32_t)((wid * 16 + (lane & 15)) * APAD + (lane >> 4) * 8) * 2;
    const uint32_t kv_off = (uint32_t)(((lane & 7)) * APAD + (lane >> 3) * 8) * 2;

    uint32_t qh[4][4], ql[4][4];   // Q fragments, loaded once

    for (int j = jlo; j < jhi; j++) {
        const int s = (j - jlo) & 1;
        cp_wait<0>();
        __syncthreads();
        if (j + 1 < jhi) { prefetch_kv(j + 1, s ^ 1); cp_commit(); }
        if (j == jlo) {
            // Q smem is ready exactly once; hoist fragments into registers
#pragma unroll
            for (int ks = 0; ks < 4; ks++) {
                ldsm4(qh[ks], smb + AQH * 2 + q_off + ks * 32);
                ldsm4(ql[ks], smb + AQL * 2 + q_off + ks * 32);
            }
        }
        if (tid < 64) {
            float ss, cc;
            sincosf((float)(j * 64 + tid) * ANG, &ss, &cc);
            cks[s * 64 + tid] = cc;
            sks[s * 64 + tid] = ss;
        }
        __syncthreads();

        const uint32_t Khs = smb + AKH * 2 + (uint32_t)s * (ATILE * 2);
        const uint32_t Kls = smb + AKL * 2 + (uint32_t)s * (ATILE * 2);
        const uint32_t Vhs = smb + AVH * 2 + (uint32_t)s * (ATILE * 2);
        const uint32_t Vls = smb + AVL * 2 + (uint32_t)s * (ATILE * 2);

        // --- S = Q K^T ---
        float sc[8][4];
#pragma unroll
        for (int nf = 0; nf < 8; nf++)
#pragma unroll
            for (int k = 0; k < 4; k++) sc[nf][k] = 0.f;

#pragma unroll
        for (int nf = 0; nf < 8; nf++) {
            const uint32_t ko = kv_off + (uint32_t)nf * (8 * APAD * 2);
            uint32_t kh[8], kl[8];
            ldsm4(kh, Khs + ko);
            ldsm4(kh + 4, Khs + ko + 64);
            ldsm4(kl, Kls + ko);
            ldsm4(kl + 4, Kls + ko + 64);
#pragma unroll
            for (int ks = 0; ks < 4; ks++) {
                mma16816(sc[nf], qh[ks][0], qh[ks][1], qh[ks][2], qh[ks][3], kh[ks * 2], kh[ks * 2 + 1]);
                mma16816(sc[nf], qh[ks][0], qh[ks][1], qh[ks][2], qh[ks][3], kl[ks * 2], kl[ks * 2 + 1]);
                mma16816(sc[nf], ql[ks][0], ql[ks][1], ql[ks][2], ql[ks][3], kh[ks * 2], kh[ks * 2 + 1]);
            }
        }

        // --- weight, mask, z, split to A-frags ---
        uint32_t ah[4][4], al[4][4];
        const bool diag = (j == i);
        const int lr0 = wid * 16 + gid, lr1 = lr0 + 8;
#pragma unroll
        for (int nf = 0; nf < 8; nf++) {
            const int c0 = nf * 8 + qid * 2, c1 = c0 + 1;
            float ck0 = cks[s * 64 + c0], sk0 = sks[s * 64 + c0];
            float ck1 = cks[s * 64 + c1], sk1 = sks[s * 64 + c1];
            float v0 = sc[nf][0] * (cq0 * ck0 + sq0 * sk0);
            float v1 = sc[nf][1] * (cq0 * ck1 + sq0 * sk1);
            float v2 = sc[nf][2] * (cq1 * ck0 + sq1 * sk0);
            float v3 = sc[nf][3] * (cq1 * ck1 + sq1 * sk1);
            if (diag) {
                if (c0 > lr0) v0 = 0.f;
                if (c1 > lr0) v1 = 0.f;
                if (c0 > lr1) v2 = 0.f;
                if (c1 > lr1) v3 = 0.f;
            }
            z0 += v0 + v1;
            z1 += v2 + v3;
            __nv_bfloat16 h0, h1, h2, h3, l0, l1, l2, l3;
            split_bf16(v0, h0, l0); split_bf16(v1, h1, l1);
            split_bf16(v2, h2, l2); split_bf16(v3, h3, l3);
            const int f = nf >> 1;
            if ((nf & 1) == 0) {
                ah[f][0] = pack2(h0, h1); ah[f][1] = pack2(h2, h3);
                al[f][0] = pack2(l0, l1); al[f][1] = pack2(l2, l3);
            } else {
                ah[f][2] = pack2(h0, h1); ah[f][3] = pack2(h2, h3);
                al[f][2] = pack2(l0, l1); al[f][3] = pack2(l2, l3);
            }
        }

        // --- O += S Vt^T ---
#pragma unroll
        for (int nf = 0; nf < 8; nf++) {
            const uint32_t vo = kv_off + (uint32_t)nf * (8 * APAD * 2);
            uint32_t vh[8], vl[8];
            ldsm4(vh, Vhs + vo);
            ldsm4(vh + 4, Vhs + vo + 64);
            ldsm4(vl, Vls + vo);
            ldsm4(vl + 4, Vls + vo + 64);
#pragma unroll
            for (int f = 0; f < 4; f++) {
                mma16816(oacc[nf], ah[f][0], ah[f][1], ah[f][2], ah[f][3], vh[f * 2], vh[f * 2 + 1]);
                mma16816(oacc[nf], al[f][0], al[f][1], al[f][2], al[f][3], vh[f * 2], vh[f * 2 + 1]);
                mma16816(oacc[nf], ah[f][0], ah[f][1], ah[f][2], ah[f][3], vl[f * 2], vl[f * 2 + 1]);
            }
        }
    }

    // z reduce over quad
    z0 += __shfl_xor_sync(0xffffffffu, z0, 1);
    z0 += __shfl_xor_sync(0xffffffffu, z0, 2);
    z1 += __shfl_xor_sync(0xffffffffu, z1, 1);
    z1 += __shfl_xor_sync(0xffffffffu, z1, 2);

    const int gr0 = qrow0 + wid * 16 + gid;
    const int gr1 = gr0 + 8;

    float* Op = seg ? g_Opart1 : g_Opart0;
    float* zp = seg ? g_zpart1 : g_zpart0;
    if (qid == 0) {
        zp[(size_t)gr0 * NHEAD + h] = z0;
        zp[(size_t)gr1 * NHEAD + h] = z1;
    }
#pragma unroll
    for (int nf = 0; nf < 8; nf++) {
        const int col = h * DKH + nf * 8 + qid * 2;
        *(float2*)(Op + (size_t)gr0 * DIMM + col) = make_float2(oacc[nf][0], oacc[nf][1]);
        *(float2*)(Op + (size_t)gr1 * DIMM + col) = make_float2(oacc[nf][2], oacc[nf][3]);
    }
}

// ---------------------------------------------------------------------------
// combine: O = (P0+P1)/max(z0+z1,1e-6) * gate -> bf16 hi/lo
// ---------------------------------------------------------------------------
__global__ void __launch_bounds__(256) combine_kernel()
{
    int i4 = (blockIdx.x * 256 + threadIdx.x) * 4;
    int row = i4 >> 9;
    int col = i4 & 511;
    int h = col >> 6;
    float z = g_zpart0[(size_t)row * NHEAD + h] + g_zpart1[(size_t)row * NHEAD + h];
    float zi = 1.f / fmaxf(z, 1e-6f);
    float4 a = *(const float4*)(g_Opart0 + i4);
    float4 bp = *(const float4*)(g_Opart1 + i4);
    float4 g = *(const float4*)(g_G + i4);
    float v0 = (a.x + bp.x) * zi * g.x;
    float v1 = (a.y + bp.y) * zi * g.y;
    float v2 = (a.z + bp.z) * zi * g.z;
    float v3 = (a.w + bp.w) * zi * g.w;
    __nv_bfloat16 h0, h1, h2, h3, l0, l1, l2, l3;
    split_bf16(v0, h0, l0); split_bf16(v1, h1, l1);
    split_bf16(v2, h2, l2); split_bf16(v3, h3, l3);
    *(__nv_bfloat162*)(g_Ohi + i4)     = __halves2bfloat162(h0, h1);
    *(__nv_bfloat162*)(g_Ohi + i4 + 2) = __halves2bfloat162(h2, h3);
    *(__nv_bfloat162*)(g_Olo + i4)     = __halves2bfloat162(l0, l1);
    *(__nv_bfloat162*)(g_Olo + i4 + 2) = __halves2bfloat162(l2, l3);
}

// ---------------------------------------------------------------------------
extern "C" void kernel_launch(void* const* d_in, const int* in_sizes, int n_in,
                              void* d_out, int out_size)
{
    const float* x  = (const float*)d_in[0];
    const float* Wq = (const float*)d_in[1];
    const float* Wk = (const float*)d_in[2];
    const float* Wv = (const float*)d_in[3];
    const float* Wo = (const float*)d_in[4];
    const float* Wg = (const float*)d_in[5];
    const float* bg = (const float*)d_in[6];

    cudaFuncSetAttribute(mma_proj_kernel, cudaFuncAttributeMaxDynamicSharedMemorySize, GEMM_SMEM_BYTES);
    cudaFuncSetAttribute(mma_out_kernel, cudaFuncAttributeMaxDynamicSharedMemorySize, GEMM_SMEM_BYTES);
    cudaFuncSetAttribute(attn3_kernel, cudaFuncAttributeMaxDynamicSharedMemorySize, ATTN2_SMEM_BYTES);

    prep_kernel<<<dim3(16, 16, 9), 256>>>(x, Wq, Wk, Wv, Wg, Wo);
    mma_proj_kernel<<<dim3(4, 16, 4), 256, GEMM_SMEM_BYTES>>>(bg);
    attn3_kernel<<<dim3(32, 8, 2), 128, ATTN2_SMEM_BYTES>>>();
    combine_kernel<<<NROWS * DIMM / 1024, 256>>>();
    mma_out_kernel<<<dim3(4, 16), 256, GEMM_SMEM_BYTES>>>((float*)d_out);
}

// round 7
// speedup vs baseline: 1.3491x; 1.3491x over previous
#include <cuda_runtime.h>
#include <cuda_fp16.h>
#include <math.h>
#include <stdint.h>

// Problem constants
#define BATCH 2
#define TSEQ  1024
#define DIMM  512
#define NHEAD 8
#define DKH   64
#define NROWS (BATCH * TSEQ)   // 2048

// ---------------------------------------------------------------------------
// Scratch (__device__ globals)
// ---------------------------------------------------------------------------
__device__ __align__(16) float g_G[NROWS * DIMM];
__device__ __align__(16) float g_Opart0[NROWS * DIMM];
__device__ __align__(16) float g_Opart1[NROWS * DIMM];
__device__ __align__(16) float g_zpart0[NROWS * NHEAD];
__device__ __align__(16) float g_zpart1[NROWS * NHEAD];

__device__ __align__(16) __half g_Xh[NROWS * DIMM];      // x single fp16
__device__ __align__(16) __half g_Qh[NROWS * DIMM];      // Q hi
__device__ __align__(16) __half g_Ql[NROWS * DIMM];      // Q lo
__device__ __align__(16) __half g_Kx[NROWS * DIMM];      // K single
__device__ __align__(16) __half g_Vtx[NROWS * DIMM];     // V single, transposed [(b*8+h)*64+d][t]
__device__ __align__(16) __half g_Ohh[NROWS * DIMM];     // combined O hi
__device__ __align__(16) __half g_Ohl[NROWS * DIMM];     // combined O lo
// transposed weights [n][k]; proj weights hi/lo, Wo single
__device__ __align__(16) __half g_Wh[4 * DIMM * DIMM];
__device__ __align__(16) __half g_Wl[4 * DIMM * DIMM];
__device__ __align__(16) __half g_Woh[DIMM * DIMM];

// ---------------------------------------------------------------------------
// helpers
// ---------------------------------------------------------------------------
__device__ __forceinline__ uint32_t smem_u32(const void* p) {
    uint32_t a;
    asm("{ .reg .u64 t; cvta.to.shared.u64 t, %1; cvt.u32.u64 %0, t; }" : "=r"(a) : "l"(p));
    return a;
}
__device__ __forceinline__ void cp_async16(uint32_t dst, const void* src) {
    asm volatile("cp.async.cg.shared.global [%0], [%1], 16;" :: "r"(dst), "l"(src));
}
__device__ __forceinline__ void cp_commit() {
    asm volatile("cp.async.commit_group;" ::: "memory");
}
template <int N>
__device__ __forceinline__ void cp_wait() {
    asm volatile("cp.async.wait_group %0;" :: "n"(N) : "memory");
}
__device__ __forceinline__ void ldsm4(uint32_t* r, uint32_t addr) {
    asm volatile("ldmatrix.sync.aligned.m8n8.x4.shared.b16 {%0,%1,%2,%3}, [%4];"
        : "=r"(r[0]), "=r"(r[1]), "=r"(r[2]), "=r"(r[3]) : "r"(addr));
}
__device__ __forceinline__ void mma16816(float* c,
                                         uint32_t a0, uint32_t a1, uint32_t a2, uint32_t a3,
                                         uint32_t b0, uint32_t b1) {
    asm volatile(
        "mma.sync.aligned.m16n8k16.row.col.f32.f16.f16.f32 "
        "{%0,%1,%2,%3}, {%4,%5,%6,%7}, {%8,%9}, {%0,%1,%2,%3};"
        : "+f"(c[0]), "+f"(c[1]), "+f"(c[2]), "+f"(c[3])
        : "r"(a0), "r"(a1), "r"(a2), "r"(a3), "r"(b0), "r"(b1));
}
__device__ __forceinline__ uint32_t f22h2(float a, float b) {
    __half2 t = __float22half2_rn(make_float2(a, b));
    return *(uint32_t*)&t;
}
__device__ __forceinline__ float2 h22f2(uint32_t p) {
    return __half22float2(*(__half2*)&p);
}
// split pair (v0,v1) -> packed hi + packed lo
__device__ __forceinline__ void split2(float v0, float v1, uint32_t& hp, uint32_t& lp) {
    hp = f22h2(v0, v1);
    float2 hb = h22f2(hp);
    lp = f22h2(v0 - hb.x, v1 - hb.y);
}

// ---------------------------------------------------------------------------
// merged preprocessing: z<5 -> weight transpose(+split); z>=5 -> x -> fp16
// ---------------------------------------------------------------------------
__global__ void __launch_bounds__(256) prep_kernel(
    const float* __restrict__ x,
    const float* __restrict__ Wq, const float* __restrict__ Wk,
    const float* __restrict__ Wv, const float* __restrict__ Wg,
    const float* __restrict__ Wo)
{
    if (blockIdx.z < 5) {
        __shared__ float t[32][33];
        const int w = blockIdx.z;
        const float* __restrict__ W = (w == 0) ? Wq : (w == 1) ? Wk : (w == 2) ? Wv : (w == 3) ? Wg : Wo;

        const int tx = threadIdx.x & 31, ty = threadIdx.x >> 5;
        const int n0 = blockIdx.x * 32, k0 = blockIdx.y * 32;
#pragma unroll
        for (int j = 0; j < 4; j++)
            t[ty + 8 * j][tx] = W[(size_t)(k0 + ty + 8 * j) * DIMM + n0 + tx];
        __syncthreads();
        if (w < 4) {
            __half* Hi = g_Wh + (size_t)w * DIMM * DIMM;
            __half* Lo = g_Wl + (size_t)w * DIMM * DIMM;
#pragma unroll
            for (int j = 0; j < 4; j++) {
                float v = t[tx][ty + 8 * j];
                __half h = __float2half(v);
                __half l = __float2half(v - __half2float(h));
                size_t o = (size_t)(n0 + ty + 8 * j) * DIMM + k0 + tx;
                Hi[o] = h; Lo[o] = l;
            }
        } else {
#pragma unroll
            for (int j = 0; j < 4; j++) {
                float v = t[tx][ty + 8 * j];
                size_t o = (size_t)(n0 + ty + 8 * j) * DIMM + k0 + tx;
                g_Woh[o] = __float2half(v);
            }
        }
    } else {
        int bid = (blockIdx.z - 5) * 256 + blockIdx.y * 16 + blockIdx.x;
        int i4 = (bid * 256 + threadIdx.x) * 4;
        float4 v = *(const float4*)(x + i4);
        *(__half2*)(g_Xh + i4)     = __float22half2_rn(make_float2(v.x, v.y));
        *(__half2*)(g_Xh + i4 + 2) = __float22half2_rn(make_float2(v.z, v.w));
    }
}

// ---------------------------------------------------------------------------
// fp16 asymmetric 2-pass HMMA GEMM (128x128 tile, K=512)
// ASPLIT=0: A single (P0), B split (P1=Bh, P2=Bl)
// ASPLIT=1: A split (P0=Ah, P1=Al), B single (P2)
// MODE: 0 float out, 1 relu->fp16 hi/lo, 2 ->transposed V single, 3 sigmoid->float, 4 relu->fp16 single
// ---------------------------------------------------------------------------
#define PADK 40
#define BUF_ELEMS (128 * PADK)
#define GEMM_SMEM_BYTES (2 * 3 * BUF_ELEMS * 2)  // 61440

template<int ASPLIT, int MODE>
__device__ __forceinline__ void mma_gemm_tile(
    const __half* __restrict__ P0, const __half* __restrict__ P1,
    const __half* __restrict__ P2,
    int m0, int n0,
    float* __restrict__ fout, __half* __restrict__ o1, __half* __restrict__ o2,
    const float* __restrict__ bias)
{
    extern __shared__ __half sm[];
    const uint32_t smb = smem_u32(sm);

    const int tid = threadIdx.x;
    const int wid = tid >> 5;
    const int lane = tid & 31;
    const int wm = wid >> 2;
    const int wn = wid & 3;
    const int gid = lane >> 2;
    const int qid = lane & 3;

    const uint32_t a_off = (uint32_t)((wm * 64 + (lane & 15)) * PADK + (lane >> 4) * 8) * 2;
    const uint32_t b_off = (uint32_t)((wn * 32 + (lane & 7)) * PADK + (lane >> 3) * 8) * 2;

    float c[4][4][4];
#pragma unroll
    for (int i = 0; i < 4; i++)
#pragma unroll
        for (int j = 0; j < 4; j++)
#pragma unroll
            for (int k = 0; k < 4; k++) c[i][j][k] = 0.f;

    const int STAGE_B = 3 * BUF_ELEMS * 2;   // bytes per stage

    auto prefetch = [&](int chunk, int stage) {
        const int k0 = chunk * 32;
#pragma unroll
        for (int t = 0; t < 2; t++) {
            int id = tid + t * 256;
            int row = id >> 2, seg = id & 3;
            uint32_t soff = (uint32_t)(row * PADK + seg * 8) * 2;
            uint32_t sb = smb + (uint32_t)stage * STAGE_B + soff;
            size_t mo = (size_t)(m0 + row) * DIMM + k0 + seg * 8;
            size_t no = (size_t)(n0 + row) * DIMM + k0 + seg * 8;
            cp_async16(sb + 0 * (BUF_ELEMS * 2), P0 + mo);
            cp_async16(sb + 1 * (BUF_ELEMS * 2), P1 + (ASPLIT ? mo : no));
            cp_async16(sb + 2 * (BUF_ELEMS * 2), P2 + no);
        }
        cp_commit();
    };

    prefetch(0, 0);

    for (int chunk = 0; chunk < 16; chunk++) {
        const int stage = chunk & 1;
        if (chunk + 1 < 16) {
            prefetch(chunk + 1, stage ^ 1);
            cp_wait<1>();
        } else {
            cp_wait<0>();
        }
        __syncthreads();

        const uint32_t s0 = smb + (uint32_t)stage * STAGE_B;
        const uint32_t s1 = s0 + BUF_ELEMS * 2;
        const uint32_t s2 = s0 + 2 * (BUF_ELEMS * 2);

        uint32_t b1[4][4], b2[4][4];
        if (ASPLIT == 0) {
#pragma unroll
            for (int nf = 0; nf < 4; nf++) {
                const uint32_t bo = b_off + (uint32_t)nf * (8 * PADK * 2);
                ldsm4(b1[nf], s1 + bo);   // Bh
                ldsm4(b2[nf], s2 + bo);   // Bl
            }
        } else {
#pragma unroll
            for (int nf = 0; nf < 4; nf++) {
                const uint32_t bo = b_off + (uint32_t)nf * (8 * PADK * 2);
                ldsm4(b1[nf], s2 + bo);   // B single
            }
        }

#pragma unroll
        for (int ks = 0; ks < 2; ks++) {
            uint32_t a1[4][4], a2[4][4];
#pragma unroll
            for (int mf = 0; mf < 4; mf++) {
                const uint32_t ao = a_off + (uint32_t)mf * (16 * PADK * 2) + (uint32_t)ks * 32;
                ldsm4(a1[mf], s0 + ao);
                if (ASPLIT == 1) ldsm4(a2[mf], s1 + ao);
            }
#pragma unroll
            for (int nf = 0; nf < 4; nf++) {
#pragma unroll
                for (int mf = 0; mf < 4; mf++) {
                    if (ASPLIT == 0) {
                        mma16816(c[mf][nf], a1[mf][0], a1[mf][1], a1[mf][2], a1[mf][3],
                                 b1[nf][ks * 2], b1[nf][ks * 2 + 1]);
                        mma16816(c[mf][nf], a1[mf][0], a1[mf][1], a1[mf][2], a1[mf][3],
                                 b2[nf][ks * 2], b2[nf][ks * 2 + 1]);
                    } else {
                        mma16816(c[mf][nf], a1[mf][0], a1[mf][1], a1[mf][2], a1[mf][3],
                                 b1[nf][ks * 2], b1[nf][ks * 2 + 1]);
                        mma16816(c[mf][nf], a2[mf][0], a2[mf][1], a2[mf][2], a2[mf][3],
                                 b1[nf][ks * 2], b1[nf][ks * 2 + 1]);
                    }
                }
            }
        }
        __syncthreads();
    }

#pragma unroll
    for (int mf = 0; mf < 4; mf++) {
#pragma unroll
        for (int nf = 0; nf < 4; nf++) {
            int m = m0 + wm * 64 + mf * 16 + gid;
            int n = n0 + wn * 32 + nf * 8 + qid * 2;
            float v0 = c[mf][nf][0], v1 = c[mf][nf][1];
            float v2 = c[mf][nf][2], v3 = c[mf][nf][3];
            if (MODE == 0) {
                *(float2*)(fout + (size_t)m * DIMM + n)       = make_float2(v0, v1);
                *(float2*)(fout + (size_t)(m + 8) * DIMM + n) = make_float2(v2, v3);
            } else if (MODE == 1) {
                v0 = fmaxf(v0, 0.f); v1 = fmaxf(v1, 0.f);
                v2 = fmaxf(v2, 0.f); v3 = fmaxf(v3, 0.f);
                uint32_t hp, lp;
                split2(v0, v1, hp, lp);
                *(uint32_t*)(o1 + (size_t)m * DIMM + n) = hp;
                *(uint32_t*)(o2 + (size_t)m * DIMM + n) = lp;
                split2(v2, v3, hp, lp);
                *(uint32_t*)(o1 + (size_t)(m + 8) * DIMM + n) = hp;
                *(uint32_t*)(o2 + (size_t)(m + 8) * DIMM + n) = lp;
            } else if (MODE == 2) {
                int bb = m >> 10, tt = m & 1023;
                int hh = n >> 6, dd = n & 63;
                size_t base = ((size_t)((bb * 8 + hh) * 64 + dd)) * 1024 + tt;
                o1[base]        = __float2half(v0);
                o1[base + 1024] = __float2half(v1);
                o1[base + 8]    = __float2half(v2);
                o1[base + 1032] = __float2half(v3);
            } else if (MODE == 3) {
                float b0 = bias[n], b1v = bias[n + 1];
                v0 = 1.f / (1.f + expf(-(v0 + b0)));
                v1 = 1.f / (1.f + expf(-(v1 + b1v)));
                v2 = 1.f / (1.f + expf(-(v2 + b0)));
                v3 = 1.f / (1.f + expf(-(v3 + b1v)));
                *(float2*)(fout + (size_t)m * DIMM + n)       = make_float2(v0, v1);
                *(float2*)(fout + (size_t)(m + 8) * DIMM + n) = make_float2(v2, v3);
            } else { // MODE 4: relu -> single fp16
                v0 = fmaxf(v0, 0.f); v1 = fmaxf(v1, 0.f);
                v2 = fmaxf(v2, 0.f); v3 = fmaxf(v3, 0.f);
                *(uint32_t*)(o1 + (size_t)m * DIMM + n)       = f22h2(v0, v1);
                *(uint32_t*)(o1 + (size_t)(m + 8) * DIMM + n) = f22h2(v2, v3);
            }
        }
    }
}

__global__ void __launch_bounds__(256) mma_proj_kernel(const float* __restrict__ bg)
{
    const int zi = blockIdx.z;
    const __half* Bh = g_Wh + (size_t)zi * DIMM * DIMM;
    const __half* Bl = g_Wl + (size_t)zi * DIMM * DIMM;
    const int m0 = blockIdx.y * 128, n0 = blockIdx.x * 128;
    if (zi == 0)
        mma_gemm_tile<0, 1>(g_Xh, Bh, Bl, m0, n0, nullptr, g_Qh, g_Ql, nullptr);
    else if (zi == 1)
        mma_gemm_tile<0, 4>(g_Xh, Bh, Bl, m0, n0, nullptr, g_Kx, nullptr, nullptr);
    else if (zi == 2)
        mma_gemm_tile<0, 2>(g_Xh, Bh, Bl, m0, n0, nullptr, g_Vtx, nullptr, nullptr);
    else
        mma_gemm_tile<0, 3>(g_Xh, Bh, Bl, m0, n0, g_G, nullptr, nullptr, bg);
}

__global__ void __launch_bounds__(256) mma_out_kernel(float* __restrict__ out)
{
    mma_gemm_tile<1, 0>(g_Ohh, g_Ohl, g_Woh, blockIdx.y * 128, blockIdx.x * 128,
                        out, nullptr, nullptr, nullptr);
}

// ---------------------------------------------------------------------------
// fp16 HMMA cosformer attention, split-K (2 segments per qtile)
// Q hi/lo (exact), K single, V single; S split in regs -> 2-pass vs V
// ---------------------------------------------------------------------------
#define APAD 72
#define ATILE (64 * APAD)              // halves per tile
#define AQH 0
#define AQL (ATILE)
#define AK  (2 * ATILE)                // + stage*ATILE (stages at 2,3)
#define AV  (4 * ATILE)                // + stage*ATILE (stages at 4,5)
#define ATRIG_C (6 * ATILE * 2)        // byte offset of trig
#define ATTN_SMEM_BYTES (6 * ATILE * 2 + 2 * 2 * 64 * 4)

__global__ void __launch_bounds__(128) attn3_kernel()
{
    extern __shared__ __half asm_[];
    const uint32_t smb = smem_u32(asm_);
    float* cks = (float*)((char*)asm_ + ATRIG_C);
    float* sks = cks + 128;

    const int i = 15 - (blockIdx.x >> 1);
    const int seg = blockIdx.x & 1;
    const int h = blockIdx.y;
    const int b = blockIdx.z;
    const int tid = threadIdx.x;
    const int wid = tid >> 5;
    const int lane = tid & 31;
    const int gid = lane >> 2;
    const int qid = lane & 3;

    const int nj = i + 1;
    const int hhalf = (nj + 1) >> 1;
    const int jlo = seg ? hhalf : 0;
    const int jhi = seg ? nj : hhalf;

    const int qrow0 = b * TSEQ + i * 64;
    const float ANG = (float)(3.14159265358979323846 / 2048.0);

    // prologue: Q hi/lo tiles
    {
#pragma unroll
        for (int t = 0; t < 4; t++) {
            int id = tid + t * 128;
            int row = id >> 3, sgm = id & 7;
            size_t src = (size_t)(qrow0 + row) * DIMM + h * DKH + sgm * 8;
            uint32_t so = (uint32_t)(row * APAD + sgm * 8) * 2;
            cp_async16(smb + AQH * 2 + so, g_Qh + src);
            cp_async16(smb + AQL * 2 + so, g_Ql + src);
        }
    }
    auto prefetch_kv = [&](int j, int s) {
#pragma unroll
        for (int t = 0; t < 4; t++) {
            int id = tid + t * 128;
            int row = id >> 3, sgm = id & 7;
            uint32_t so = (uint32_t)(row * APAD + sgm * 8) * 2 + (uint32_t)s * (ATILE * 2);
            size_t ksrc = (size_t)(b * TSEQ + j * 64 + row) * DIMM + h * DKH + sgm * 8;
            cp_async16(smb + AK * 2 + so, g_Kx + ksrc);
            size_t vsrc = (size_t)((b * 8 + h) * 64 + row) * TSEQ + j * 64 + sgm * 8;
            cp_async16(smb + AV * 2 + so, g_Vtx + vsrc);
        }
    };
    if (jlo < jhi) prefetch_kv(jlo, 0);
    cp_commit();

    float cq0, sq0, cq1, sq1;
    {
        float a0 = (float)(i * 64 + wid * 16 + gid) * ANG;
        float a1 = (float)(i * 64 + wid * 16 + gid + 8) * ANG;
        sincosf(a0, &sq0, &cq0);
        sincosf(a1, &sq1, &cq1);
    }

    float oacc[8][4];
#pragma unroll
    for (int nf = 0; nf < 8; nf++)
#pragma unroll
        for (int k = 0; k < 4; k++) oacc[nf][k] = 0.f;
    float z0 = 0.f, z1 = 0.f;

    const uint32_t q_off = (uint32_t)((wid * 16 + (lane & 15)) * APAD + (lane >> 4) * 8) * 2;
    const uint32_t kv_off = (uint32_t)(((lane & 7)) * APAD + (lane >> 3) * 8) * 2;

    uint32_t qh[4][4], ql[4][4];

    for (int j = jlo; j < jhi; j++) {
        const int s = (j - jlo) & 1;
        cp_wait<0>();
        __syncthreads();
        if (j + 1 < jhi) { prefetch_kv(j + 1, s ^ 1); cp_commit(); }
        if (j == jlo) {
#pragma unroll
            for (int ks = 0; ks < 4; ks++) {
                ldsm4(qh[ks], smb + AQH * 2 + q_off + ks * 32);
                ldsm4(ql[ks], smb + AQL * 2 + q_off + ks * 32);
            }
        }
        if (tid < 64) {
            float ss, cc;
            sincosf((float)(j * 64 + tid) * ANG, &ss, &cc);
            cks[s * 64 + tid] = cc;
            sks[s * 64 + tid] = ss;
        }
        __syncthreads();

        const uint32_t Ks = smb + AK * 2 + (uint32_t)s * (ATILE * 2);
        const uint32_t Vs = smb + AV * 2 + (uint32_t)s * (ATILE * 2);

        // --- S = Q K^T  (Qh + Ql passes vs single K) ---
        float sc[8][4];
#pragma unroll
        for (int nf = 0; nf < 8; nf++)
#pragma unroll
            for (int k = 0; k < 4; k++) sc[nf][k] = 0.f;

#pragma unroll
        for (int nf = 0; nf < 8; nf++) {
            const uint32_t ko = kv_off + (uint32_t)nf * (8 * APAD * 2);
            uint32_t kf[8];
            ldsm4(kf, Ks + ko);
            ldsm4(kf + 4, Ks + ko + 64);
#pragma unroll
            for (int ks = 0; ks < 4; ks++) {
                mma16816(sc[nf], qh[ks][0], qh[ks][1], qh[ks][2], qh[ks][3], kf[ks * 2], kf[ks * 2 + 1]);
                mma16816(sc[nf], ql[ks][0], ql[ks][1], ql[ks][2], ql[ks][3], kf[ks * 2], kf[ks * 2 + 1]);
            }
        }

        // --- weight, mask, z, split to A-frags (fp16 hi/lo) ---
        uint32_t ah[4][4], al[4][4];
        const bool diag = (j == i);
        const int lr0 = wid * 16 + gid, lr1 = lr0 + 8;
#pragma unroll
        for (int nf = 0; nf < 8; nf++) {
            const int c0 = nf * 8 + qid * 2, c1 = c0 + 1;
            float ck0 = cks[s * 64 + c0], sk0 = sks[s * 64 + c0];
            float ck1 = cks[s * 64 + c1], sk1 = sks[s * 64 + c1];
            float v0 = sc[nf][0] * (cq0 * ck0 + sq0 * sk0);
            float v1 = sc[nf][1] * (cq0 * ck1 + sq0 * sk1);
            float v2 = sc[nf][2] * (cq1 * ck0 + sq1 * sk0);
            float v3 = sc[nf][3] * (cq1 * ck1 + sq1 * sk1);
            if (diag) {
                if (c0 > lr0) v0 = 0.f;
                if (c1 > lr0) v1 = 0.f;
                if (c0 > lr1) v2 = 0.f;
                if (c1 > lr1) v3 = 0.f;
            }
            z0 += v0 + v1;
            z1 += v2 + v3;
            uint32_t hp01, lp01, hp23, lp23;
            split2(v0, v1, hp01, lp01);
            split2(v2, v3, hp23, lp23);
            const int f = nf >> 1;
            if ((nf & 1) == 0) {
                ah[f][0] = hp01; ah[f][1] = hp23;
                al[f][0] = lp01; al[f][1] = lp23;
            } else {
                ah[f][2] = hp01; ah[f][3] = hp23;
                al[f][2] = lp01; al[f][3] = lp23;
            }
        }

        // --- O += S Vt^T  (Sh + Sl passes vs single V) ---
#pragma unroll
        for (int nf = 0; nf < 8; nf++) {
            const uint32_t vo = kv_off + (uint32_t)nf * (8 * APAD * 2);
            uint32_t vf[8];
            ldsm4(vf, Vs + vo);
            ldsm4(vf + 4, Vs + vo + 64);
#pragma unroll
            for (int f = 0; f < 4; f++) {
                mma16816(oacc[nf], ah[f][0], ah[f][1], ah[f][2], ah[f][3], vf[f * 2], vf[f * 2 + 1]);
                mma16816(oacc[nf], al[f][0], al[f][1], al[f][2], al[f][3], vf[f * 2], vf[f * 2 + 1]);
            }
        }
    }

    // z reduce over quad
    z0 += __shfl_xor_sync(0xffffffffu, z0, 1);
    z0 += __shfl_xor_sync(0xffffffffu, z0, 2);
    z1 += __shfl_xor_sync(0xffffffffu, z1, 1);
    z1 += __shfl_xor_sync(0xffffffffu, z1, 2);

    const int gr0 = qrow0 + wid * 16 + gid;
    const int gr1 = gr0 + 8;

    float* Op = seg ? g_Opart1 : g_Opart0;
    float* zp = seg ? g_zpart1 : g_zpart0;
    if (qid == 0) {
        zp[(size_t)gr0 * NHEAD + h] = z0;
        zp[(size_t)gr1 * NHEAD + h] = z1;
    }
#pragma unroll
    for (int nf = 0; nf < 8; nf++) {
        const int col = h * DKH + nf * 8 + qid * 2;
        *(float2*)(Op + (size_t)gr0 * DIMM + col) = make_float2(oacc[nf][0], oacc[nf][1]);
        *(float2*)(Op + (size_t)gr1 * DIMM + col) = make_float2(oacc[nf][2], oacc[nf][3]);
    }
}

// ---------------------------------------------------------------------------
// combine: O = (P0+P1)/max(z0+z1,1e-6) * gate -> fp16 hi/lo
// ---------------------------------------------------------------------------
__global__ void __launch_bounds__(256) combine_kernel()
{
    int i4 = (blockIdx.x * 256 + threadIdx.x) * 4;
    int row = i4 >> 9;
    int col = i4 & 511;
    int h = col >> 6;
    float z = g_zpart0[(size_t)row * NHEAD + h] + g_zpart1[(size_t)row * NHEAD + h];
    float zi = 1.f / fmaxf(z, 1e-6f);
    float4 a = *(const float4*)(g_Opart0 + i4);
    float4 bp = *(const float4*)(g_Opart1 + i4);
    float4 g = *(const float4*)(g_G + i4);
    float v0 = (a.x + bp.x) * zi * g.x;
    float v1 = (a.y + bp.y) * zi * g.y;
    float v2 = (a.z + bp.z) * zi * g.z;
    float v3 = (a.w + bp.w) * zi * g.w;
    uint32_t hp, lp;
    split2(v0, v1, hp, lp);
    *(uint32_t*)(g_Ohh + i4)     = hp;
    *(uint32_t*)(g_Ohl + i4)     = lp;
    split2(v2, v3, hp, lp);
    *(uint32_t*)(g_Ohh + i4 + 2) = hp;
    *(uint32_t*)(g_Ohl + i4 + 2) = lp;
}

// ---------------------------------------------------------------------------
extern "C" void kernel_launch(void* const* d_in, const int* in_sizes, int n_in,
                              void* d_out, int out_size)
{
    const float* x  = (const float*)d_in[0];
    const float* Wq = (const float*)d_in[1];
    const float* Wk = (const float*)d_in[2];
    const float* Wv = (const float*)d_in[3];
    const float* Wo = (const float*)d_in[4];
    const float* Wg = (const float*)d_in[5];
    const float* bg = (const float*)d_in[6];

    cudaFuncSetAttribute(mma_proj_kernel, cudaFuncAttributeMaxDynamicSharedMemorySize, GEMM_SMEM_BYTES);
    cudaFuncSetAttribute(mma_out_kernel, cudaFuncAttributeMaxDynamicSharedMemorySize, GEMM_SMEM_BYTES);
    cudaFuncSetAttribute(attn3_kernel, cudaFuncAttributeMaxDynamicSharedMemorySize, ATTN_SMEM_BYTES);

    prep_kernel<<<dim3(16, 16, 9), 256>>>(x, Wq, Wk, Wv, Wg, Wo);
    mma_proj_kernel<<<dim3(4, 16, 4), 256, GEMM_SMEM_BYTES>>>(bg);
    attn3_kernel<<<dim3(32, 8, 2), 128, ATTN_SMEM_BYTES>>>();
    combine_kernel<<<NROWS * DIMM / 1024, 256>>>();
    mma_out_kernel<<<dim3(4, 16), 256, GEMM_SMEM_BYTES>>>((float*)d_out);
}

// round 8
// speedup vs baseline: 1.5330x; 1.1363x over previous
#include <cuda_runtime.h>
#include <cuda_fp16.h>
#include <math.h>
#include <stdint.h>

// Problem constants
#define BATCH 2
#define TSEQ  1024
#define DIMM  512
#define NHEAD 8
#define DKH   64
#define NROWS (BATCH * TSEQ)   // 2048

// ---------------------------------------------------------------------------
// Scratch (__device__ globals)
// ---------------------------------------------------------------------------
__device__ __align__(16) float  g_G[NROWS * DIMM];
__device__ __align__(16) __half g_Xh[NROWS * DIMM];     // x single fp16
__device__ __align__(16) __half g_Qx[NROWS * DIMM];     // Q single
__device__ __align__(16) __half g_Kx[NROWS * DIMM];     // K single
__device__ __align__(16) __half g_Vtx[NROWS * DIMM];    // V single, transposed [(b*8+h)*64+d][t]
__device__ __align__(16) __half g_Ohh[NROWS * DIMM];    // gated O hi
__device__ __align__(16) __half g_Ohl[NROWS * DIMM];    // gated O lo
__device__ __align__(16) __half g_Wqh[DIMM * DIMM];     // Wq^T hi
__device__ __align__(16) __half g_Wql[DIMM * DIMM];     // Wq^T lo
__device__ __align__(16) __half g_Ws[4 * DIMM * DIMM];  // Wk,Wv,Wg,Wo ^T single

// ---------------------------------------------------------------------------
// helpers
// ---------------------------------------------------------------------------
__device__ __forceinline__ uint32_t smem_u32(const void* p) {
    uint32_t a;
    asm("{ .reg .u64 t; cvta.to.shared.u64 t, %1; cvt.u32.u64 %0, t; }" : "=r"(a) : "l"(p));
    return a;
}
__device__ __forceinline__ void cp_async16(uint32_t dst, const void* src) {
    asm volatile("cp.async.cg.shared.global [%0], [%1], 16;" :: "r"(dst), "l"(src));
}
__device__ __forceinline__ void cp_commit() {
    asm volatile("cp.async.commit_group;" ::: "memory");
}
template <int N>
__device__ __forceinline__ void cp_wait() {
    asm volatile("cp.async.wait_group %0;" :: "n"(N) : "memory");
}
__device__ __forceinline__ void ldsm4(uint32_t* r, uint32_t addr) {
    asm volatile("ldmatrix.sync.aligned.m8n8.x4.shared.b16 {%0,%1,%2,%3}, [%4];"
        : "=r"(r[0]), "=r"(r[1]), "=r"(r[2]), "=r"(r[3]) : "r"(addr));
}
__device__ __forceinline__ void mma16816(float* c,
                                         uint32_t a0, uint32_t a1, uint32_t a2, uint32_t a3,
                                         uint32_t b0, uint32_t b1) {
    asm volatile(
        "mma.sync.aligned.m16n8k16.row.col.f32.f16.f16.f32 "
        "{%0,%1,%2,%3}, {%4,%5,%6,%7}, {%8,%9}, {%0,%1,%2,%3};"
        : "+f"(c[0]), "+f"(c[1]), "+f"(c[2]), "+f"(c[3])
        : "r"(a0), "r"(a1), "r"(a2), "r"(a3), "r"(b0), "r"(b1));
}
__device__ __forceinline__ uint32_t f22h2(float a, float b) {
    __half2 t = __float22half2_rn(make_float2(a, b));
    return *(uint32_t*)&t;
}
__device__ __forceinline__ void split2(float v0, float v1, uint32_t& hp, uint32_t& lp) {
    hp = f22h2(v0, v1);
    float2 hb = __half22float2(*(__half2*)&hp);
    lp = f22h2(v0 - hb.x, v1 - hb.y);
}

// ---------------------------------------------------------------------------
// prep: z<5 -> weight transpose (+split for Wq); z>=5 -> x -> fp16
// ---------------------------------------------------------------------------
__global__ void __launch_bounds__(256) prep_kernel(
    const float* __restrict__ x,
    const float* __restrict__ Wq, const float* __restrict__ Wk,
    const float* __restrict__ Wv, const float* __restrict__ Wg,
    const float* __restrict__ Wo)
{
    if (blockIdx.z < 5) {
        __shared__ float t[32][33];
        const int w = blockIdx.z;
        const float* __restrict__ W = (w == 0) ? Wq : (w == 1) ? Wk : (w == 2) ? Wv : (w == 3) ? Wg : Wo;

        const int tx = threadIdx.x & 31, ty = threadIdx.x >> 5;
        const int n0 = blockIdx.x * 32, k0 = blockIdx.y * 32;
#pragma unroll
        for (int j = 0; j < 4; j++)
            t[ty + 8 * j][tx] = W[(size_t)(k0 + ty + 8 * j) * DIMM + n0 + tx];
        __syncthreads();
        if (w == 0) {
#pragma unroll
            for (int j = 0; j < 4; j++) {
                float v = t[tx][ty + 8 * j];
                __half h = __float2half(v);
                __half l = __float2half(v - __half2float(h));
                size_t o = (size_t)(n0 + ty + 8 * j) * DIMM + k0 + tx;
                g_Wqh[o] = h; g_Wql[o] = l;
            }
        } else {
            __half* Ws = g_Ws + (size_t)(w - 1) * DIMM * DIMM;
#pragma unroll
            for (int j = 0; j < 4; j++) {
                float v = t[tx][ty + 8 * j];
                size_t o = (size_t)(n0 + ty + 8 * j) * DIMM + k0 + tx;
                Ws[o] = __float2half(v);
            }
        }
    } else {
        int bid = (blockIdx.z - 5) * 256 + blockIdx.y * 16 + blockIdx.x;
        int i4 = (bid * 256 + threadIdx.x) * 4;
        float4 v = *(const float4*)(x + i4);
        *(__half2*)(g_Xh + i4)     = __float22half2_rn(make_float2(v.x, v.y));
        *(__half2*)(g_Xh + i4 + 2) = __float22half2_rn(make_float2(v.z, v.w));
    }
}

// ---------------------------------------------------------------------------
// HMMA GEMM template (128x128 tile, K=512)
// VAR 0: A single + B split hi/lo (2-pass)  [Q projection]
// VAR 1: A single + B single (1-pass)       [K, V, G projections]
// VAR 2: A split hi/lo + B single (2-pass)  [output GEMM]
// MODE 0: float out; 2: transposed V single; 3: sigmoid+bias float; 4: relu single
// ---------------------------------------------------------------------------
#define PADK 40
#define BUF_ELEMS (128 * PADK)
#define BUF_B (BUF_ELEMS * 2)
#define STAGE_B (3 * BUF_B)
#define GEMM_SMEM_BYTES (2 * STAGE_B)  // 61440

template<int VAR, int MODE>
__device__ __forceinline__ void mma_gemm_tile(
    const __half* __restrict__ A0, const __half* __restrict__ A1,
    const __half* __restrict__ B0, const __half* __restrict__ B1,
    int m0, int n0,
    float* __restrict__ fout, __half* __restrict__ o1,
    const float* __restrict__ bias)
{
    extern __shared__ __half sm[];
    const uint32_t smb = smem_u32(sm);

    const int tid = threadIdx.x;
    const int wid = tid >> 5;
    const int lane = tid & 31;
    const int wm = wid >> 2;
    const int wn = wid & 3;
    const int gid = lane >> 2;
    const int qid = lane & 3;

    const uint32_t a_off = (uint32_t)((wm * 64 + (lane & 15)) * PADK + (lane >> 4) * 8) * 2;
    const uint32_t b_off = (uint32_t)((wn * 32 + (lane & 7)) * PADK + (lane >> 3) * 8) * 2;

    float c[4][4][4];
#pragma unroll
    for (int i = 0; i < 4; i++)
#pragma unroll
        for (int j = 0; j < 4; j++)
#pragma unroll
            for (int k = 0; k < 4; k++) c[i][j][k] = 0.f;

    auto prefetch = [&](int chunk, int stage) {
        const int k0 = chunk * 32;
#pragma unroll
        for (int t = 0; t < 2; t++) {
            int id = tid + t * 256;
            int row = id >> 2, seg = id & 3;
            uint32_t soff = (uint32_t)(row * PADK + seg * 8) * 2;
            uint32_t sb = smb + (uint32_t)stage * STAGE_B + soff;
            size_t mo = (size_t)(m0 + row) * DIMM + k0 + seg * 8;
            size_t no = (size_t)(n0 + row) * DIMM + k0 + seg * 8;
            cp_async16(sb, A0 + mo);
            if (VAR == 2) cp_async16(sb + BUF_B, A1 + mo);
            else          cp_async16(sb + BUF_B, B0 + no);
            if (VAR == 0) cp_async16(sb + 2 * BUF_B, B1 + no);
            if (VAR == 2) cp_async16(sb + 2 * BUF_B, B0 + no);
        }
        cp_commit();
    };

    prefetch(0, 0);

    for (int chunk = 0; chunk < 16; chunk++) {
        const int stage = chunk & 1;
        if (chunk + 1 < 16) {
            prefetch(chunk + 1, stage ^ 1);
            cp_wait<1>();
        } else {
            cp_wait<0>();
        }
        __syncthreads();

        const uint32_t s0 = smb + (uint32_t)stage * STAGE_B;
        const uint32_t s1 = s0 + BUF_B;
        const uint32_t s2 = s0 + 2 * BUF_B;

        uint32_t b1[4][4], b2[4][4];
#pragma unroll
        for (int nf = 0; nf < 4; nf++) {
            const uint32_t bo = b_off + (uint32_t)nf * (8 * PADK * 2);
            if (VAR == 0) { ldsm4(b1[nf], s1 + bo); ldsm4(b2[nf], s2 + bo); }
            if (VAR == 1) { ldsm4(b1[nf], s1 + bo); }
            if (VAR == 2) { ldsm4(b1[nf], s2 + bo); }
        }

#pragma unroll
        for (int ks = 0; ks < 2; ks++) {
            uint32_t a1[4][4], a2[4][4];
#pragma unroll
            for (int mf = 0; mf < 4; mf++) {
                const uint32_t ao = a_off + (uint32_t)mf * (16 * PADK * 2) + (uint32_t)ks * 32;
                ldsm4(a1[mf], s0 + ao);
                if (VAR == 2) ldsm4(a2[mf], s1 + ao);
            }
#pragma unroll
            for (int nf = 0; nf < 4; nf++) {
                const uint32_t p0 = b1[nf][ks * 2], p1 = b1[nf][ks * 2 + 1];
#pragma unroll
                for (int mf = 0; mf < 4; mf++) {
                    mma16816(c[mf][nf], a1[mf][0], a1[mf][1], a1[mf][2], a1[mf][3], p0, p1);
                    if (VAR == 0)
                        mma16816(c[mf][nf], a1[mf][0], a1[mf][1], a1[mf][2], a1[mf][3],
                                 b2[nf][ks * 2], b2[nf][ks * 2 + 1]);
                    if (VAR == 2)
                        mma16816(c[mf][nf], a2[mf][0], a2[mf][1], a2[mf][2], a2[mf][3], p0, p1);
                }
            }
        }
        __syncthreads();
    }

#pragma unroll
    for (int mf = 0; mf < 4; mf++) {
#pragma unroll
        for (int nf = 0; nf < 4; nf++) {
            int m = m0 + wm * 64 + mf * 16 + gid;
            int n = n0 + wn * 32 + nf * 8 + qid * 2;
            float v0 = c[mf][nf][0], v1 = c[mf][nf][1];
            float v2 = c[mf][nf][2], v3 = c[mf][nf][3];
            if (MODE == 0) {
                *(float2*)(fout + (size_t)m * DIMM + n)       = make_float2(v0, v1);
                *(float2*)(fout + (size_t)(m + 8) * DIMM + n) = make_float2(v2, v3);
            } else if (MODE == 2) {
                int bb = m >> 10, tt = m & 1023;
                int hh = n >> 6, dd = n & 63;
                size_t base = ((size_t)((bb * 8 + hh) * 64 + dd)) * 1024 + tt;
                o1[base]        = __float2half(v0);
                o1[base + 1024] = __float2half(v1);
                o1[base + 8]    = __float2half(v2);
                o1[base + 1032] = __float2half(v3);
            } else if (MODE == 3) {
                float b0 = bias[n], b1v = bias[n + 1];
                v0 = 1.f / (1.f + expf(-(v0 + b0)));
                v1 = 1.f / (1.f + expf(-(v1 + b1v)));
                v2 = 1.f / (1.f + expf(-(v2 + b0)));
                v3 = 1.f / (1.f + expf(-(v3 + b1v)));
                *(float2*)(fout + (size_t)m * DIMM + n)       = make_float2(v0, v1);
                *(float2*)(fout + (size_t)(m + 8) * DIMM + n) = make_float2(v2, v3);
            } else { // MODE 4: relu -> single fp16
                v0 = fmaxf(v0, 0.f); v1 = fmaxf(v1, 0.f);
                v2 = fmaxf(v2, 0.f); v3 = fmaxf(v3, 0.f);
                *(uint32_t*)(o1 + (size_t)m * DIMM + n)       = f22h2(v0, v1);
                *(uint32_t*)(o1 + (size_t)(m + 8) * DIMM + n) = f22h2(v2, v3);
            }
        }
    }
}

__global__ void __launch_bounds__(256) mma_proj_kernel(const float* __restrict__ bg)
{
    const int zi = blockIdx.z;
    const int m0 = blockIdx.y * 128, n0 = blockIdx.x * 128;
    if (zi == 0)
        mma_gemm_tile<0, 4>(g_Xh, nullptr, g_Wqh, g_Wql, m0, n0, nullptr, g_Qx, nullptr);
    else if (zi == 1)
        mma_gemm_tile<1, 4>(g_Xh, nullptr, g_Ws + 0 * DIMM * DIMM, nullptr, m0, n0, nullptr, g_Kx, nullptr);
    else if (zi == 2)
        mma_gemm_tile<1, 2>(g_Xh, nullptr, g_Ws + 1 * DIMM * DIMM, nullptr, m0, n0, nullptr, g_Vtx, nullptr);
    else
        mma_gemm_tile<1, 3>(g_Xh, nullptr, g_Ws + 2 * DIMM * DIMM, nullptr, m0, n0, g_G, nullptr, bg);
}

__global__ void __launch_bounds__(256) mma_out_kernel(float* __restrict__ out)
{
    mma_gemm_tile<2, 0>(g_Ohh, g_Ohl, g_Ws + 3 * DIMM * DIMM, nullptr,
                        blockIdx.y * 128, blockIdx.x * 128, out, nullptr, nullptr);
}

// ---------------------------------------------------------------------------
// fp16 HMMA cosformer attention: 32-row q-tiles, full causal range per CTA,
// fused normalize+gate epilogue writing O hi/lo directly. grid (32,8,2), 128 thr
// ---------------------------------------------------------------------------
#define APAD 72
#define AQ_H   0                     // Q: 32*72 halves
#define AK_H   2304                  // K stages: 2 x 64*72
#define AV_H   11520                 // V stages: 2 x 64*72
#define TRIG_B 41472                 // cks[2][64], sks[2][64] floats
#define ORED_B 4608                  // alias over K stages (epilogue only)
#define ATTN_SMEM_BYTES (41472 + 1024)

__global__ void __launch_bounds__(128) attn4_kernel()
{
    extern __shared__ __half asm_[];
    const uint32_t smb = smem_u32(asm_);
    float* cks = (float*)((char*)asm_ + TRIG_B);
    float* sks = cks + 128;

    const int i = 31 - blockIdx.x;   // longest first
    const int h = blockIdx.y;
    const int b = blockIdx.z;
    const int tid = threadIdx.x;
    const int wid = tid >> 5;
    const int lane = tid & 31;
    const int gid = lane >> 2;
    const int qid = lane & 3;
    const int wm = wid & 1;          // 16-row half
    const int wn = wid >> 1;         // 32-col half

    const int jhi = (i >> 1) + 1;
    const int qrow0 = b * TSEQ + i * 32;
    const float ANG = (float)(3.14159265358979323846 / 2048.0);

    // Q tile load (single fp16, 32x64)
#pragma unroll
    for (int t = 0; t < 2; t++) {
        int id = tid + t * 128;
        int row = id >> 3, seg = id & 7;
        cp_async16(smb + (uint32_t)(row * APAD + seg * 8) * 2,
                   g_Qx + (size_t)(qrow0 + row) * DIMM + h * DKH + seg * 8);
    }
    auto prefetch_kv = [&](int j, int s) {
#pragma unroll
        for (int t = 0; t < 4; t++) {
            int id = tid + t * 128;
            int row = id >> 3, seg = id & 7;
            uint32_t so = (uint32_t)(row * APAD + seg * 8) * 2;
            cp_async16(smb + (AK_H + s * 4608) * 2 + so,
                       g_Kx + (size_t)(b * TSEQ + j * 64 + row) * DIMM + h * DKH + seg * 8);
            cp_async16(smb + (AV_H + s * 4608) * 2 + so,
                       g_Vtx + (size_t)((b * 8 + h) * 64 + row) * TSEQ + j * 64 + seg * 8);
        }
    };
    prefetch_kv(0, 0);
    cp_commit();

    float cq0, sq0, cq1, sq1;
    {
        float a0 = (float)(i * 32 + wm * 16 + gid) * ANG;
        float a1 = (float)(i * 32 + wm * 16 + gid + 8) * ANG;
        sincosf(a0, &sq0, &cq0);
        sincosf(a1, &sq1, &cq1);
    }

    float oacc[8][4];
#pragma unroll
    for (int nf = 0; nf < 8; nf++)
#pragma unroll
        for (int k = 0; k < 4; k++) oacc[nf][k] = 0.f;
    float z0 = 0.f, z1 = 0.f;

    const uint32_t q_off = (uint32_t)((wm * 16 + (lane & 15)) * APAD + (lane >> 4) * 8) * 2;
    uint32_t qf[4][4];

    const int lr0 = i * 32 + wm * 16 + gid;   // global q rows
    const int lr1 = lr0 + 8;

    for (int j = 0; j < jhi; j++) {
        const int s = j & 1;
        cp_wait<0>();
        __syncthreads();
        if (j + 1 < jhi) { prefetch_kv(j + 1, s ^ 1); cp_commit(); }
        if (j == 0) {
#pragma unroll
            for (int ks = 0; ks < 4; ks++)
                ldsm4(qf[ks], smb + q_off + ks * 32);
        }
        if (tid < 64) {
            float ss, cc;
            sincosf((float)(j * 64 + tid) * ANG, &ss, &cc);
            cks[s * 64 + tid] = cc;
            sks[s * 64 + tid] = ss;
        }
        __syncthreads();

        const uint32_t Ks = smb + (AK_H + s * 4608) * 2;
        const uint32_t Vs = smb + (AV_H + s * 4608) * 2;

        // --- S = Q K^T (single pass, 16 MMAs/warp) ---
        float sc[4][4];
#pragma unroll
        for (int nf = 0; nf < 4; nf++)
#pragma unroll
            for (int k = 0; k < 4; k++) sc[nf][k] = 0.f;

#pragma unroll
        for (int nf = 0; nf < 4; nf++) {
            const uint32_t ko = Ks + (uint32_t)((wn * 32 + nf * 8 + (lane & 7)) * APAD + (lane >> 3) * 8) * 2;
            uint32_t kf[8];
            ldsm4(kf, ko);
            ldsm4(kf + 4, ko + 64);
#pragma unroll
            for (int ks = 0; ks < 4; ks++)
                mma16816(sc[nf], qf[ks][0], qf[ks][1], qf[ks][2], qf[ks][3], kf[ks * 2], kf[ks * 2 + 1]);
        }

        // --- weight, mask, z, pack single fp16 A-frags ---
        uint32_t af[2][4];
        const bool diag = (j == jhi - 1);
#pragma unroll
        for (int nf = 0; nf < 4; nf++) {
            const int cl0 = wn * 32 + nf * 8 + qid * 2, cl1 = cl0 + 1;
            const int cg0 = j * 64 + cl0, cg1 = cg0 + 1;
            float ck0 = cks[s * 64 + cl0], sk0 = sks[s * 64 + cl0];
            float ck1 = cks[s * 64 + cl1], sk1 = sks[s * 64 + cl1];
            float v0 = sc[nf][0] * (cq0 * ck0 + sq0 * sk0);
            float v1 = sc[nf][1] * (cq0 * ck1 + sq0 * sk1);
            float v2 = sc[nf][2] * (cq1 * ck0 + sq1 * sk0);
            float v3 = sc[nf][3] * (cq1 * ck1 + sq1 * sk1);
            if (diag) {
                if (cg0 > lr0) v0 = 0.f;
                if (cg1 > lr0) v1 = 0.f;
                if (cg0 > lr1) v2 = 0.f;
                if (cg1 > lr1) v3 = 0.f;
            }
            z0 += v0 + v1;
            z1 += v2 + v3;
            const int f = nf >> 1;
            if ((nf & 1) == 0) {
                af[f][0] = f22h2(v0, v1); af[f][1] = f22h2(v2, v3);
            } else {
                af[f][2] = f22h2(v0, v1); af[f][3] = f22h2(v2, v3);
            }
        }

        // --- O += S Vt^T (single pass, 16 MMAs/warp) ---
#pragma unroll
        for (int nfv = 0; nfv < 8; nfv++) {
            const uint32_t vo = Vs + (uint32_t)((nfv * 8 + (lane & 7)) * APAD + wn * 32 + (lane >> 3) * 8) * 2;
            uint32_t vf[4];
            ldsm4(vf, vo);
#pragma unroll
            for (int f = 0; f < 2; f++)
                mma16816(oacc[nfv], af[f][0], af[f][1], af[f][2], af[f][3], vf[f * 2], vf[f * 2 + 1]);
        }
    }

    // quad-reduce z (cols within quad)
    z0 += __shfl_xor_sync(0xffffffffu, z0, 1);
    z0 += __shfl_xor_sync(0xffffffffu, z0, 2);
    z1 += __shfl_xor_sync(0xffffffffu, z1, 1);
    z1 += __shfl_xor_sync(0xffffffffu, z1, 2);

    __syncthreads();  // all warps done with K smem -> safe to alias Ored

    float* Ored = (float*)((char*)asm_ + ORED_B);    // [2][32][66]
    float* zred = (float*)((char*)asm_ + TRIG_B);    // [2][32]
    {
        const int r0 = wm * 16 + gid;
#pragma unroll
        for (int nfv = 0; nfv < 8; nfv++) {
            const int c = nfv * 8 + qid * 2;
            Ored[wn * 2112 + r0 * 66 + c]           = oacc[nfv][0];
            Ored[wn * 2112 + r0 * 66 + c + 1]       = oacc[nfv][1];
            Ored[wn * 2112 + (r0 + 8) * 66 + c]     = oacc[nfv][2];
            Ored[wn * 2112 + (r0 + 8) * 66 + c + 1] = oacc[nfv][3];
        }
        if (qid == 0) {
            zred[wn * 32 + r0]     = z0;
            zred[wn * 32 + r0 + 8] = z1;
        }
    }
    __syncthreads();

    // cooperative finish: normalize, gate, split to fp16 hi/lo
    {
        const int r = tid >> 2;
        const int cbase = (tid & 3) * 16;
        float z = zred[r] + zred[32 + r];
        float zinv = 1.f / fmaxf(z, 1e-6f);
        size_t gb = (size_t)(qrow0 + r) * DIMM + h * DKH + cbase;
#pragma unroll
        for (int p = 0; p < 8; p++) {
            const int c = cbase + p * 2;
            float va = Ored[r * 66 + c]     + Ored[2112 + r * 66 + c];
            float vb = Ored[r * 66 + c + 1] + Ored[2112 + r * 66 + c + 1];
            float2 g = *(const float2*)(g_G + gb + p * 2);
            va *= zinv * g.x;
            vb *= zinv * g.y;
            uint32_t hp, lp;
            split2(va, vb, hp, lp);
            *(uint32_t*)(g_Ohh + gb + p * 2) = hp;
            *(uint32_t*)(g_Ohl + gb + p * 2) = lp;
        }
    }
}

// ---------------------------------------------------------------------------
extern "C" void kernel_launch(void* const* d_in, const int* in_sizes, int n_in,
                              void* d_out, int out_size)
{
    const float* x  = (const float*)d_in[0];
    const float* Wq = (const float*)d_in[1];
    const float* Wk = (const float*)d_in[2];
    const float* Wv = (const float*)d_in[3];
    const float* Wo = (const float*)d_in[4];
    const float* Wg = (const float*)d_in[5];
    const float* bg = (const float*)d_in[6];

    cudaFuncSetAttribute(mma_proj_kernel, cudaFuncAttributeMaxDynamicSharedMemorySize, GEMM_SMEM_BYTES);
    cudaFuncSetAttribute(mma_out_kernel, cudaFuncAttributeMaxDynamicSharedMemorySize, GEMM_SMEM_BYTES);
    cudaFuncSetAttribute(attn4_kernel, cudaFuncAttributeMaxDynamicSharedMemorySize, ATTN_SMEM_BYTES);

    prep_kernel<<<dim3(16, 16, 9), 256>>>(x, Wq, Wk, Wv, Wg, Wo);
    mma_proj_kernel<<<dim3(4, 16, 4), 256, GEMM_SMEM_BYTES>>>(bg);
    attn4_kernel<<<dim3(32, 8, 2), 128, ATTN_SMEM_BYTES>>>();
    mma_out_kernel<<<dim3(4, 16), 256, GEMM_SMEM_BYTES>>>((float*)d_out);
}

// round 9
// speedup vs baseline: 1.8341x; 1.1964x over previous
#include <cuda_runtime.h>
#include <cuda_fp16.h>
#include <math.h>
#include <stdint.h>

// Problem constants
#define BATCH 2
#define TSEQ  1024
#define DIMM  512
#define NHEAD 8
#define DKH   64
#define NROWS (BATCH * TSEQ)   // 2048

// ---------------------------------------------------------------------------
// Scratch (__device__ globals)
// ---------------------------------------------------------------------------
__device__ __align__(16) float  g_G[NROWS * DIMM];
__device__ __align__(16) __half g_Xh[NROWS * DIMM];     // x single fp16
__device__ __align__(16) __half g_Qx[NROWS * DIMM];     // Q single
__device__ __align__(16) __half g_Kx[NROWS * DIMM];     // K single
__device__ __align__(16) __half g_Vtx[NROWS * DIMM];    // V single, transposed [(b*8+h)*64+d][t]
__device__ __align__(16) __half g_Ohh[NROWS * DIMM];    // gated O hi
__device__ __align__(16) __half g_Ohl[NROWS * DIMM];    // gated O lo
__device__ __align__(16) __half g_Wqh[DIMM * DIMM];     // Wq^T hi
__device__ __align__(16) __half g_Wql[DIMM * DIMM];     // Wq^T lo
__device__ __align__(16) __half g_Ws[4 * DIMM * DIMM];  // Wk,Wv,Wg,Wo ^T single

// ---------------------------------------------------------------------------
// helpers
// ---------------------------------------------------------------------------
__device__ __forceinline__ uint32_t smem_u32(const void* p) {
    uint32_t a;
    asm("{ .reg .u64 t; cvta.to.shared.u64 t, %1; cvt.u32.u64 %0, t; }" : "=r"(a) : "l"(p));
    return a;
}
__device__ __forceinline__ void cp_async16(uint32_t dst, const void* src) {
    asm volatile("cp.async.cg.shared.global [%0], [%1], 16;" :: "r"(dst), "l"(src));
}
__device__ __forceinline__ void cp_commit() {
    asm volatile("cp.async.commit_group;" ::: "memory");
}
template <int N>
__device__ __forceinline__ void cp_wait() {
    asm volatile("cp.async.wait_group %0;" :: "n"(N) : "memory");
}
__device__ __forceinline__ void ldsm4(uint32_t* r, uint32_t addr) {
    asm volatile("ldmatrix.sync.aligned.m8n8.x4.shared.b16 {%0,%1,%2,%3}, [%4];"
        : "=r"(r[0]), "=r"(r[1]), "=r"(r[2]), "=r"(r[3]) : "r"(addr));
}
__device__ __forceinline__ void mma16816(float* c,
                                         uint32_t a0, uint32_t a1, uint32_t a2, uint32_t a3,
                                         uint32_t b0, uint32_t b1) {
    asm volatile(
        "mma.sync.aligned.m16n8k16.row.col.f32.f16.f16.f32 "
        "{%0,%1,%2,%3}, {%4,%5,%6,%7}, {%8,%9}, {%0,%1,%2,%3};"
        : "+f"(c[0]), "+f"(c[1]), "+f"(c[2]), "+f"(c[3])
        : "r"(a0), "r"(a1), "r"(a2), "r"(a3), "r"(b0), "r"(b1));
}
__device__ __forceinline__ uint32_t f22h2(float a, float b) {
    __half2 t = __float22half2_rn(make_float2(a, b));
    return *(uint32_t*)&t;
}
__device__ __forceinline__ void split2(float v0, float v1, uint32_t& hp, uint32_t& lp) {
    hp = f22h2(v0, v1);
    float2 hb = __half22float2(*(__half2*)&hp);
    lp = f22h2(v0 - hb.x, v1 - hb.y);
}

// ---------------------------------------------------------------------------
// prep: z<5 -> weight transpose (+split for Wq); z>=5 -> x -> fp16
// ---------------------------------------------------------------------------
__global__ void __launch_bounds__(256) prep_kernel(
    const float* __restrict__ x,
    const float* __restrict__ Wq, const float* __restrict__ Wk,
    const float* __restrict__ Wv, const float* __restrict__ Wg,
    const float* __restrict__ Wo)
{
    if (blockIdx.z < 5) {
        __shared__ float t[32][33];
        const int w = blockIdx.z;
        const float* __restrict__ W = (w == 0) ? Wq : (w == 1) ? Wk : (w == 2) ? Wv : (w == 3) ? Wg : Wo;

        const int tx = threadIdx.x & 31, ty = threadIdx.x >> 5;
        const int n0 = blockIdx.x * 32, k0 = blockIdx.y * 32;
#pragma unroll
        for (int j = 0; j < 4; j++)
            t[ty + 8 * j][tx] = W[(size_t)(k0 + ty + 8 * j) * DIMM + n0 + tx];
        __syncthreads();
        if (w == 0) {
#pragma unroll
            for (int j = 0; j < 4; j++) {
                float v = t[tx][ty + 8 * j];
                __half h = __float2half(v);
                __half l = __float2half(v - __half2float(h));
                size_t o = (size_t)(n0 + ty + 8 * j) * DIMM + k0 + tx;
                g_Wqh[o] = h; g_Wql[o] = l;
            }
        } else {
            __half* Ws = g_Ws + (size_t)(w - 1) * DIMM * DIMM;
#pragma unroll
            for (int j = 0; j < 4; j++) {
                float v = t[tx][ty + 8 * j];
                size_t o = (size_t)(n0 + ty + 8 * j) * DIMM + k0 + tx;
                Ws[o] = __float2half(v);
            }
        }
    } else {
        int bid = (blockIdx.z - 5) * 256 + blockIdx.y * 16 + blockIdx.x;
        int i4 = (bid * 256 + threadIdx.x) * 4;
        float4 v = *(const float4*)(x + i4);
        *(__half2*)(g_Xh + i4)     = __float22half2_rn(make_float2(v.x, v.y));
        *(__half2*)(g_Xh + i4 + 2) = __float22half2_rn(make_float2(v.z, v.w));
    }
}

// ---------------------------------------------------------------------------
// HMMA GEMM template: 64x128 (MxN) tile, K=512, 8 warps (2m x 4n), warp 32x32
// VAR 0: A single + B split hi/lo (2-pass)  [Q projection]
// VAR 1: A single + B single (1-pass)       [K, V, G projections]
// VAR 2: A split hi/lo + B single (2-pass)  [output GEMM]
// MODE 0: float out; 2: transposed V single; 3: sigmoid+bias float; 4: relu single
// ---------------------------------------------------------------------------
#define PADK 40
#define BUFA_B (64 * PADK * 2)          // 5120 bytes
#define BUFB_B (128 * PADK * 2)         // 10240 bytes
#define R1OFF  BUFA_B                   // 5120
#define R2OFF  (BUFA_B + BUFB_B)        // 15360
#define STAGE_B (BUFA_B + 2 * BUFB_B)   // 25600
#define GEMM_SMEM_BYTES (2 * STAGE_B)   // 51200

template<int VAR, int MODE>
__device__ __forceinline__ void mma_gemm_tile(
    const __half* __restrict__ A0, const __half* __restrict__ A1,
    const __half* __restrict__ B0, const __half* __restrict__ B1,
    int m0, int n0,
    float* __restrict__ fout, __half* __restrict__ o1,
    const float* __restrict__ bias)
{
    extern __shared__ __half sm[];
    const uint32_t smb = smem_u32(sm);

    const int tid = threadIdx.x;
    const int wid = tid >> 5;
    const int lane = tid & 31;
    const int wm = wid >> 2;          // 0..1  (32-row half)
    const int wn = wid & 3;           // 0..3  (32-col quarter)
    const int gid = lane >> 2;
    const int qid = lane & 3;

    const uint32_t a_off = (uint32_t)((wm * 32 + (lane & 15)) * PADK + (lane >> 4) * 8) * 2;
    const uint32_t b_off = (uint32_t)((wn * 32 + (lane & 7)) * PADK + (lane >> 3) * 8) * 2;

    float c[2][4][4];
#pragma unroll
    for (int i = 0; i < 2; i++)
#pragma unroll
        for (int j = 0; j < 4; j++)
#pragma unroll
            for (int k = 0; k < 4; k++) c[i][j][k] = 0.f;

    auto prefetch = [&](int chunk, int stage) {
        const int k0 = chunk * 32;
        const uint32_t sbase = smb + (uint32_t)stage * STAGE_B;
        // A region: 64 rows x 32 cols
        {
            int row = tid >> 2, seg = tid & 3;
            uint32_t soff = (uint32_t)(row * PADK + seg * 8) * 2;
            size_t mo = (size_t)(m0 + row) * DIMM + k0 + seg * 8;
            cp_async16(sbase + soff, A0 + mo);
            if (VAR == 2) cp_async16(sbase + R1OFF + soff, A1 + mo);
        }
        // B region: 128 rows x 32 cols
#pragma unroll
        for (int t = 0; t < 2; t++) {
            int id = tid + t * 256;
            int row = id >> 2, seg = id & 3;
            uint32_t soff = (uint32_t)(row * PADK + seg * 8) * 2;
            size_t no = (size_t)(n0 + row) * DIMM + k0 + seg * 8;
            if (VAR == 0) {
                cp_async16(sbase + R1OFF + soff, B0 + no);
                cp_async16(sbase + R2OFF + soff, B1 + no);
            } else if (VAR == 1) {
                cp_async16(sbase + R1OFF + soff, B0 + no);
            } else {
                cp_async16(sbase + R2OFF + soff, B0 + no);
            }
        }
        cp_commit();
    };

    prefetch(0, 0);

    for (int chunk = 0; chunk < 16; chunk++) {
        const int stage = chunk & 1;
        if (chunk + 1 < 16) {
            prefetch(chunk + 1, stage ^ 1);
            cp_wait<1>();
        } else {
            cp_wait<0>();
        }
        __syncthreads();

        const uint32_t s0 = smb + (uint32_t)stage * STAGE_B;

        // B fragments (full K=32 chunk)
        uint32_t b1[4][4], b2[4][4];
#pragma unroll
        for (int nf = 0; nf < 4; nf++) {
            const uint32_t bo = b_off + (uint32_t)nf * (8 * PADK * 2);
            if (VAR == 0) { ldsm4(b1[nf], s0 + R1OFF + bo); ldsm4(b2[nf], s0 + R2OFF + bo); }
            if (VAR == 1) { ldsm4(b1[nf], s0 + R1OFF + bo); }
            if (VAR == 2) { ldsm4(b1[nf], s0 + R2OFF + bo); }
        }

#pragma unroll
        for (int ks = 0; ks < 2; ks++) {
            uint32_t a1[2][4], a2[2][4];
#pragma unroll
            for (int mf = 0; mf < 2; mf++) {
                const uint32_t ao = a_off + (uint32_t)mf * (16 * PADK * 2) + (uint32_t)ks * 32;
                ldsm4(a1[mf], s0 + ao);
                if (VAR == 2) ldsm4(a2[mf], s0 + R1OFF + ao);
            }
#pragma unroll
            for (int nf = 0; nf < 4; nf++) {
                const uint32_t p0 = b1[nf][ks * 2], p1 = b1[nf][ks * 2 + 1];
#pragma unroll
                for (int mf = 0; mf < 2; mf++) {
                    mma16816(c[mf][nf], a1[mf][0], a1[mf][1], a1[mf][2], a1[mf][3], p0, p1);
                    if (VAR == 0)
                        mma16816(c[mf][nf], a1[mf][0], a1[mf][1], a1[mf][2], a1[mf][3],
                                 b2[nf][ks * 2], b2[nf][ks * 2 + 1]);
                    if (VAR == 2)
                        mma16816(c[mf][nf], a2[mf][0], a2[mf][1], a2[mf][2], a2[mf][3], p0, p1);
                }
            }
        }
        __syncthreads();
    }

#pragma unroll
    for (int mf = 0; mf < 2; mf++) {
#pragma unroll
        for (int nf = 0; nf < 4; nf++) {
            int m = m0 + wm * 32 + mf * 16 + gid;
            int n = n0 + wn * 32 + nf * 8 + qid * 2;
            float v0 = c[mf][nf][0], v1 = c[mf][nf][1];
            float v2 = c[mf][nf][2], v3 = c[mf][nf][3];
            if (MODE == 0) {
                *(float2*)(fout + (size_t)m * DIMM + n)       = make_float2(v0, v1);
                *(float2*)(fout + (size_t)(m + 8) * DIMM + n) = make_float2(v2, v3);
            } else if (MODE == 2) {
                int bb = m >> 10, tt = m & 1023;
                int hh = n >> 6, dd = n & 63;
                size_t base = ((size_t)((bb * 8 + hh) * 64 + dd)) * 1024 + tt;
                o1[base]        = __float2half(v0);
                o1[base + 1024] = __float2half(v1);
                o1[base + 8]    = __float2half(v2);
                o1[base + 1032] = __float2half(v3);
            } else if (MODE == 3) {
                float b0 = bias[n], b1v = bias[n + 1];
                v0 = 1.f / (1.f + expf(-(v0 + b0)));
                v1 = 1.f / (1.f + expf(-(v1 + b1v)));
                v2 = 1.f / (1.f + expf(-(v2 + b0)));
                v3 = 1.f / (1.f + expf(-(v3 + b1v)));
                *(float2*)(fout + (size_t)m * DIMM + n)       = make_float2(v0, v1);
                *(float2*)(fout + (size_t)(m + 8) * DIMM + n) = make_float2(v2, v3);
            } else { // MODE 4: relu -> single fp16
                v0 = fmaxf(v0, 0.f); v1 = fmaxf(v1, 0.f);
                v2 = fmaxf(v2, 0.f); v3 = fmaxf(v3, 0.f);
                *(uint32_t*)(o1 + (size_t)m * DIMM + n)       = f22h2(v0, v1);
                *(uint32_t*)(o1 + (size_t)(m + 8) * DIMM + n) = f22h2(v2, v3);
            }
        }
    }
}

__global__ void __launch_bounds__(256) mma_proj_kernel(const float* __restrict__ bg)
{
    const int zi = blockIdx.z;
    const int m0 = blockIdx.y * 64, n0 = blockIdx.x * 128;
    if (zi == 0)
        mma_gemm_tile<0, 4>(g_Xh, nullptr, g_Wqh, g_Wql, m0, n0, nullptr, g_Qx, nullptr);
    else if (zi == 1)
        mma_gemm_tile<1, 4>(g_Xh, nullptr, g_Ws + 0 * DIMM * DIMM, nullptr, m0, n0, nullptr, g_Kx, nullptr);
    else if (zi == 2)
        mma_gemm_tile<1, 2>(g_Xh, nullptr, g_Ws + 1 * DIMM * DIMM, nullptr, m0, n0, nullptr, g_Vtx, nullptr);
    else
        mma_gemm_tile<1, 3>(g_Xh, nullptr, g_Ws + 2 * DIMM * DIMM, nullptr, m0, n0, g_G, nullptr, bg);
}

__global__ void __launch_bounds__(256) mma_out_kernel(float* __restrict__ out)
{
    mma_gemm_tile<2, 0>(g_Ohh, g_Ohl, g_Ws + 3 * DIMM * DIMM, nullptr,
                        blockIdx.y * 64, blockIdx.x * 128, out, nullptr, nullptr);
}

// ---------------------------------------------------------------------------
// fp16 HMMA cosformer attention: 32-row q-tiles, full causal range per CTA,
// fused normalize+gate epilogue writing O hi/lo directly. grid (32,8,2), 128 thr
// ---------------------------------------------------------------------------
#define APAD 72
#define AQ_H   0                     // Q: 32*72 halves
#define AK_H   2304                  // K stages: 2 x 64*72
#define AV_H   11520                 // V stages: 2 x 64*72
#define TRIG_B 41472                 // cks[2][64], sks[2][64] floats
#define ORED_B 4608                  // alias over K stages (epilogue only)
#define ATTN_SMEM_BYTES (41472 + 1024)

__global__ void __launch_bounds__(128) attn4_kernel()
{
    extern __shared__ __half asm_[];
    const uint32_t smb = smem_u32(asm_);
    float* cks = (float*)((char*)asm_ + TRIG_B);
    float* sks = cks + 128;

    const int i = 31 - blockIdx.x;   // longest first
    const int h = blockIdx.y;
    const int b = blockIdx.z;
    const int tid = threadIdx.x;
    const int wid = tid >> 5;
    const int lane = tid & 31;
    const int gid = lane >> 2;
    const int qid = lane & 3;
    const int wm = wid & 1;          // 16-row half
    const int wn = wid >> 1;         // 32-col half

    const int jhi = (i >> 1) + 1;
    const int qrow0 = b * TSEQ + i * 32;
    const float ANG = (float)(3.14159265358979323846 / 2048.0);

    // Q tile load (single fp16, 32x64)
#pragma unroll
    for (int t = 0; t < 2; t++) {
        int id = tid + t * 128;
        int row = id >> 3, seg = id & 7;
        cp_async16(smb + (uint32_t)(row * APAD + seg * 8) * 2,
                   g_Qx + (size_t)(qrow0 + row) * DIMM + h * DKH + seg * 8);
    }
    auto prefetch_kv = [&](int j, int s) {
#pragma unroll
        for (int t = 0; t < 4; t++) {
            int id = tid + t * 128;
            int row = id >> 3, seg = id & 7;
            uint32_t so = (uint32_t)(row * APAD + seg * 8) * 2;
            cp_async16(smb + (AK_H + s * 4608) * 2 + so,
                       g_Kx + (size_t)(b * TSEQ + j * 64 + row) * DIMM + h * DKH + seg * 8);
            cp_async16(smb + (AV_H + s * 4608) * 2 + so,
                       g_Vtx + (size_t)((b * 8 + h) * 64 + row) * TSEQ + j * 64 + seg * 8);
        }
    };
    prefetch_kv(0, 0);
    cp_commit();

    float cq0, sq0, cq1, sq1;
    {
        float a0 = (float)(i * 32 + wm * 16 + gid) * ANG;
        float a1 = (float)(i * 32 + wm * 16 + gid + 8) * ANG;
        sincosf(a0, &sq0, &cq0);
        sincosf(a1, &sq1, &cq1);
    }

    float oacc[8][4];
#pragma unroll
    for (int nf = 0; nf < 8; nf++)
#pragma unroll
        for (int k = 0; k < 4; k++) oacc[nf][k] = 0.f;
    float z0 = 0.f, z1 = 0.f;

    const uint32_t q_off = (uint32_t)((wm * 16 + (lane & 15)) * APAD + (lane >> 4) * 8) * 2;
    uint32_t qf[4][4];

    const int lr0 = i * 32 + wm * 16 + gid;   // global q rows
    const int lr1 = lr0 + 8;

    for (int j = 0; j < jhi; j++) {
        const int s = j & 1;
        cp_wait<0>();
        __syncthreads();
        if (j + 1 < jhi) { prefetch_kv(j + 1, s ^ 1); cp_commit(); }
        if (j == 0) {
#pragma unroll
            for (int ks = 0; ks < 4; ks++)
                ldsm4(qf[ks], smb + q_off + ks * 32);
        }
        if (tid < 64) {
            float ss, cc;
            sincosf((float)(j * 64 + tid) * ANG, &ss, &cc);
            cks[s * 64 + tid] = cc;
            sks[s * 64 + tid] = ss;
        }
        __syncthreads();

        const uint32_t Ks = smb + (AK_H + s * 4608) * 2;
        const uint32_t Vs = smb + (AV_H + s * 4608) * 2;

        // --- S = Q K^T (single pass) ---
        float sc[4][4];
#pragma unroll
        for (int nf = 0; nf < 4; nf++)
#pragma unroll
            for (int k = 0; k < 4; k++) sc[nf][k] = 0.f;

#pragma unroll
        for (int nf = 0; nf < 4; nf++) {
            const uint32_t ko = Ks + (uint32_t)((wn * 32 + nf * 8 + (lane & 7)) * APAD + (lane >> 3) * 8) * 2;
            uint32_t kf[8];
            ldsm4(kf, ko);
            ldsm4(kf + 4, ko + 64);
#pragma unroll
            for (int ks = 0; ks < 4; ks++)
                mma16816(sc[nf], qf[ks][0], qf[ks][1], qf[ks][2], qf[ks][3], kf[ks * 2], kf[ks * 2 + 1]);
        }

        // --- weight, mask, z, pack single fp16 A-frags ---
        uint32_t af[2][4];
        const bool diag = (j == jhi - 1);
#pragma unroll
        for (int nf = 0; nf < 4; nf++) {
            const int cl0 = wn * 32 + nf * 8 + qid * 2, cl1 = cl0 + 1;
            const int cg0 = j * 64 + cl0, cg1 = cg0 + 1;
            float ck0 = cks[s * 64 + cl0], sk0 = sks[s * 64 + cl0];
            float ck1 = cks[s * 64 + cl1], sk1 = sks[s * 64 + cl1];
            float v0 = sc[nf][0] * (cq0 * ck0 + sq0 * sk0);
            float v1 = sc[nf][1] * (cq0 * ck1 + sq0 * sk1);
            float v2 = sc[nf][2] * (cq1 * ck0 + sq1 * sk0);
            float v3 = sc[nf][3] * (cq1 * ck1 + sq1 * sk1);
            if (diag) {
                if (cg0 > lr0) v0 = 0.f;
                if (cg1 > lr0) v1 = 0.f;
                if (cg0 > lr1) v2 = 0.f;
                if (cg1 > lr1) v3 = 0.f;
            }
            z0 += v0 + v1;
            z1 += v2 + v3;
            const int f = nf >> 1;
            if ((nf & 1) == 0) {
                af[f][0] = f22h2(v0, v1); af[f][1] = f22h2(v2, v3);
            } else {
                af[f][2] = f22h2(v0, v1); af[f][3] = f22h2(v2, v3);
            }
        }

        // --- O += S Vt^T (single pass) ---
#pragma unroll
        for (int nfv = 0; nfv < 8; nfv++) {
            const uint32_t vo = Vs + (uint32_t)((nfv * 8 + (lane & 7)) * APAD + wn * 32 + (lane >> 3) * 8) * 2;
            uint32_t vf[4];
            ldsm4(vf, vo);
#pragma unroll
            for (int f = 0; f < 2; f++)
                mma16816(oacc[nfv], af[f][0], af[f][1], af[f][2], af[f][3], vf[f * 2], vf[f * 2 + 1]);
        }
    }

    // quad-reduce z (cols within quad)
    z0 += __shfl_xor_sync(0xffffffffu, z0, 1);
    z0 += __shfl_xor_sync(0xffffffffu, z0, 2);
    z1 += __shfl_xor_sync(0xffffffffu, z1, 1);
    z1 += __shfl_xor_sync(0xffffffffu, z1, 2);

    __syncthreads();  // all warps done with K smem -> safe to alias Ored

    float* Ored = (float*)((char*)asm_ + ORED_B);    // [2][32][66]
    float* zred = (float*)((char*)asm_ + TRIG_B);    // [2][32]
    {
        const int r0 = wm * 16 + gid;
#pragma unroll
        for (int nfv = 0; nfv < 8; nfv++) {
            const int c = nfv * 8 + qid * 2;
            Ored[wn * 2112 + r0 * 66 + c]           = oacc[nfv][0];
            Ored[wn * 2112 + r0 * 66 + c + 1]       = oacc[nfv][1];
            Ored[wn * 2112 + (r0 + 8) * 66 + c]     = oacc[nfv][2];
            Ored[wn * 2112 + (r0 + 8) * 66 + c + 1] = oacc[nfv][3];
        }
        if (qid == 0) {
            zred[wn * 32 + r0]     = z0;
            zred[wn * 32 + r0 + 8] = z1;
        }
    }
    __syncthreads();

    // cooperative finish: normalize, gate, split to fp16 hi/lo
    {
        const int r = tid >> 2;
        const int cbase = (tid & 3) * 16;
        float z = zred[r] + zred[32 + r];
        float zinv = 1.f / fmaxf(z, 1e-6f);
        size_t gb = (size_t)(qrow0 + r) * DIMM + h * DKH + cbase;
#pragma unroll
        for (int p = 0; p < 8; p++) {
            const int c = cbase + p * 2;
            float va = Ored[r * 66 + c]     + Ored[2112 + r * 66 + c];
            float vb = Ored[r * 66 + c + 1] + Ored[2112 + r * 66 + c + 1];
            float2 g = *(const float2*)(g_G + gb + p * 2);
            va *= zinv * g.x;
            vb *= zinv * g.y;
            uint32_t hp, lp;
            split2(va, vb, hp, lp);
            *(uint32_t*)(g_Ohh + gb + p * 2) = hp;
            *(uint32_t*)(g_Ohl + gb + p * 2) = lp;
        }
    }
}

// ---------------------------------------------------------------------------
extern "C" void kernel_launch(void* const* d_in, const int* in_sizes, int n_in,
                              void* d_out, int out_size)
{
    const float* x  = (const float*)d_in[0];
    const float* Wq = (const float*)d_in[1];
    const float* Wk = (const float*)d_in[2];
    const float* Wv = (const float*)d_in[3];
    const float* Wo = (const float*)d_in[4];
    const float* Wg = (const float*)d_in[5];
    const float* bg = (const float*)d_in[6];

    cudaFuncSetAttribute(mma_proj_kernel, cudaFuncAttributeMaxDynamicSharedMemorySize, GEMM_SMEM_BYTES);
    cudaFuncSetAttribute(mma_out_kernel, cudaFuncAttributeMaxDynamicSharedMemorySize, GEMM_SMEM_BYTES);
    cudaFuncSetAttribute(attn4_kernel, cudaFuncAttributeMaxDynamicSharedMemorySize, ATTN_SMEM_BYTES);

    prep_kernel<<<dim3(16, 16, 9), 256>>>(x, Wq, Wk, Wv, Wg, Wo);
    mma_proj_kernel<<<dim3(4, 32, 4), 256, GEMM_SMEM_BYTES>>>(bg);
    attn4_kernel<<<dim3(32, 8, 2), 128, ATTN_SMEM_BYTES>>>();
    mma_out_kernel<<<dim3(4, 32), 256, GEMM_SMEM_BYTES>>>((float*)d_out);
}